// round 8
// baseline (speedup 1.0000x reference)
#include <cuda_runtime.h>

#define HW      200704          // 448*448
#define WID     448
#define CC      64
#define BATCH   2
#define TG2     3136            // 56*56
#define P2      196
#define P2P     200             // padded q-dim for 8-aligned tiles
#define NPB     12845056        // C*HW per batch
#define SPB     65536           // S per batch
#define EPSV    1e-5f
#define GRIDK   74
#define KCHUNK  886             // ceil(65536/74)

typedef unsigned long long u64;
__device__ __forceinline__ u64 pack2(float lo, float hi) {
    u64 r; asm("mov.b64 %0,{%1,%2};" : "=l"(r) : "f"(lo), "f"(hi)); return r;
}
__device__ __forceinline__ void unpack2(u64 v, float& lo, float& hi) {
    asm("mov.b64 {%0,%1},%2;" : "=f"(lo), "=f"(hi) : "l"(v));
}
__device__ __forceinline__ u64 fma2(u64 a, u64 b, u64 c) {
    u64 d; asm("fma.rn.f32x2 %0,%1,%2,%3;" : "=l"(d) : "l"(a), "l"(b), "l"(c)); return d;
}

// ---------------- scratch ----------------
__device__ float g_q[BATCH * NPB];
__device__ float g_k[BATCH * NPB];
__device__ float g_v[BATCH * NPB];
__device__ float g_hin[BATCH * NPB];
__device__ float g_spart[BATCH * 784 * 2];
__device__ float g_stats[BATCH * 2];
__device__ float g_px[BATCH * CC * TG2];
__device__ float g_qg[BATCH * TG2 * CC];
__device__ float g_kg[BATCH * TG2 * CC];
__device__ float g_vg[BATCH * TG2 * CC];
__device__ float g_wmp[BATCH * GRIDK * P2 * P2];
__device__ float g_wmT[BATCH * P2 * P2P];    // wmT[k][q], q padded to 200 (pads stay 0)
__device__ float g_wg[(size_t)BATCH * TG2 * TG2];
__device__ float g_hg[BATCH * TG2 * CC];

// ---------------- K1: 8x8 avg-pool of x + GN stat partials ----------------
__global__ __launch_bounds__(256) void k_pool_stats(const float* __restrict__ x) {
    int b = blockIdx.y;
    int idx = blockIdx.x * 256 + threadIdx.x;
    int c = idx / TG2;
    int cell = idx - c * TG2;
    int th = cell / 56, tw = cell - th * 56;
    const float* xp = x + ((size_t)b * CC + c) * HW + (size_t)(th * 8) * WID + tw * 8;
    float s = 0.f, s2 = 0.f;
#pragma unroll
    for (int r = 0; r < 8; r++) {
        float4 a = *(const float4*)(xp + r * WID);
        float4 bb = *(const float4*)(xp + r * WID + 4);
        s  += a.x + a.y + a.z + a.w + bb.x + bb.y + bb.z + bb.w;
        s2 += a.x*a.x + a.y*a.y + a.z*a.z + a.w*a.w
            + bb.x*bb.x + bb.y*bb.y + bb.z*bb.z + bb.w*bb.w;
    }
    g_px[(b * CC + c) * TG2 + cell] = s * (1.f / 64.f);

    __shared__ float r0[256], r1[256];
    int t = threadIdx.x;
    r0[t] = s; r1[t] = s2;
    __syncthreads();
    for (int o = 128; o > 0; o >>= 1) {
        if (t < o) { r0[t] += r0[t + o]; r1[t] += r1[t + o]; }
        __syncthreads();
    }
    if (t == 0) {
        g_spart[(b * 784 + blockIdx.x) * 2 + 0] = r0[0];
        g_spart[(b * 784 + blockIdx.x) * 2 + 1] = r1[0];
    }
}

// ---------------- K2: reduce stat partials ----------------
__global__ void k_stats2() {
    int b = blockIdx.x, t = threadIdx.x;
    float s = 0.f, s2 = 0.f;
    for (int i = t; i < 784; i += 256) {
        s  += g_spart[(b * 784 + i) * 2 + 0];
        s2 += g_spart[(b * 784 + i) * 2 + 1];
    }
    __shared__ float r0[256], r1[256];
    r0[t] = s; r1[t] = s2;
    __syncthreads();
    for (int o = 128; o > 0; o >>= 1) {
        if (t < o) { r0[t] += r0[t + o]; r1[t] += r1[t + o]; }
        __syncthreads();
    }
    if (t == 0) { g_stats[b * 2] = r0[0]; g_stats[b * 2 + 1] = r1[0]; }
}

// ---------------- K3: pooled qkv from pooled x ----------------
__global__ void k_qkvg(const float* __restrict__ gnw, const float* __restrict__ gnb,
                       const float* __restrict__ qw, const float* __restrict__ qb,
                       const float* __restrict__ kw, const float* __restrict__ kb,
                       const float* __restrict__ vw, const float* __restrict__ vb) {
    int b = blockIdx.y, cell = blockIdx.x, o = threadIdx.x;
    float mean = g_stats[b * 2] * (1.f / (float)NPB);
    float var  = g_stats[b * 2 + 1] * (1.f / (float)NPB) - mean * mean;
    float inv  = rsqrtf(var + EPSV);
    __shared__ float xn[64];
    xn[o] = (g_px[(b * CC + o) * TG2 + cell] - mean) * inv * gnw[o] + gnb[o];
    __syncthreads();
    float aq = qb[o], ak = kb[o], av = vb[o];
#pragma unroll 8
    for (int j = 0; j < 64; j++) {
        float xv = xn[j];
        aq += qw[o * 64 + j] * xv;
        ak += kw[o * 64 + j] * xv;
        av += vw[o * 64 + j] * xv;
    }
    int off = (b * TG2 + cell) * CC + o;
    g_qg[off] = aq; g_kg[off] = ak; g_vg[off] = av;
}

// ---------------- K4: GN + q/k/v convs, 8x8 tiles, FFMA2 inner ----------------
__global__ __launch_bounds__(128) void k_qkv(const float* __restrict__ x,
                                             const float* __restrict__ gnw, const float* __restrict__ gnb,
                                             const float* __restrict__ W0, const float* __restrict__ B0,
                                             const float* __restrict__ W1, const float* __restrict__ B1,
                                             const float* __restrict__ W2, const float* __restrict__ B2) {
    __shared__ __align__(16) float sXn[64][128];
    __shared__ __align__(16) float sWt[64][64];
    __shared__ float sB[64];
    int b = blockIdx.y;
    int pix0 = blockIdx.x * 128;
    int t = threadIdx.x;
    float mean = g_stats[b * 2] * (1.f / (float)NPB);
    float inv  = rsqrtf(g_stats[b * 2 + 1] * (1.f / (float)NPB) - mean * mean + EPSV);

    for (int i = t; i < 2048; i += 128) {
        int c = i >> 5, p4 = i & 31;
        float4 v = *(const float4*)(x + ((size_t)b * CC + c) * HW + pix0 + p4 * 4);
        float gw = gnw[c] * inv, gb = gnb[c] - mean * gnw[c] * inv;
        v.x = v.x * gw + gb; v.y = v.y * gw + gb;
        v.z = v.z * gw + gb; v.w = v.w * gw + gb;
        *(float4*)&sXn[c][p4 * 4] = v;
    }
    const float* Ws[3] = {W0, W1, W2};
    const float* Bs[3] = {B0, B1, B2};
    float* Os[3] = {g_q, g_k, g_v};
    int og = t >> 4, pg = t & 15;

    for (int m = 0; m < 3; m++) {
        __syncthreads();
        for (int i = t; i < 1024; i += 128) {
            int o = i & 63, c4 = i >> 6;
            float4 w = *(const float4*)(Ws[m] + o * 64 + c4 * 4);
            sWt[c4 * 4 + 0][o] = w.x;
            sWt[c4 * 4 + 1][o] = w.y;
            sWt[c4 * 4 + 2][o] = w.z;
            sWt[c4 * 4 + 3][o] = w.w;
        }
        if (t < 64) sB[t] = Bs[m][t];
        __syncthreads();

        u64 accp[8][4];
#pragma unroll
        for (int i = 0; i < 8; i++) {
            int o = og * 4 + ((i < 4) ? i : 28 + i);
            u64 bp = pack2(sB[o], sB[o]);
            accp[i][0] = bp; accp[i][1] = bp; accp[i][2] = bp; accp[i][3] = bp;
        }
#pragma unroll 8
        for (int c = 0; c < 64; c++) {
            const u64* xp = (const u64*)&sXn[c][pg * 4];
            const u64* xq = (const u64*)&sXn[c][pg * 4 + 64];
            u64 x0 = xp[0], x1 = xp[1], x2 = xq[0], x3 = xq[1];
            float4 w0 = *(const float4*)&sWt[c][og * 4];
            float4 w1 = *(const float4*)&sWt[c][og * 4 + 32];
            float aw[8] = {w0.x, w0.y, w0.z, w0.w, w1.x, w1.y, w1.z, w1.w};
#pragma unroll
            for (int i = 0; i < 8; i++) {
                u64 ad = pack2(aw[i], aw[i]);
                accp[i][0] = fma2(ad, x0, accp[i][0]);
                accp[i][1] = fma2(ad, x1, accp[i][1]);
                accp[i][2] = fma2(ad, x2, accp[i][2]);
                accp[i][3] = fma2(ad, x3, accp[i][3]);
            }
        }
        float* O = Os[m];
#pragma unroll
        for (int i = 0; i < 8; i++) {
            int o = og * 4 + ((i < 4) ? i : 28 + i);
            size_t base = ((size_t)b * CC + o) * HW + pix0;
            float l0, h0, l1, h1;
            unpack2(accp[i][0], l0, h0); unpack2(accp[i][1], l1, h1);
            *(float4*)(O + base + pg * 4) = make_float4(l0, h0, l1, h1);
            unpack2(accp[i][2], l0, h0); unpack2(accp[i][3], l1, h1);
            *(float4*)(O + base + 64 + pg * 4) = make_float4(l0, h0, l1, h1);
        }
    }
}

// ---------------- K5: wm split-K GEMM, 8x8 tiles, FFMA2, dup-q smem ----------
__global__ __launch_bounds__(640, 1) void k_wm() {
    int b = blockIdx.y, kb = blockIdx.x;
    int s0 = kb * KCHUNK;
    int send = min(s0 + KCHUNK, SPB);
    const float* Q = g_q + (size_t)b * NPB;
    const float* K = g_k + (size_t)b * NPB;
    __shared__ __align__(16) float qsD[16][400];   // duplicated pairs {q,q}
    __shared__ __align__(16) float ks[16][200];
    int t = threadIdx.x;
    int ty = t / 25, tx = t - (t / 25) * 25;       // workers t<625: 25x25 grid of 8x8 tiles
    u64 accp[8][4];
#pragma unroll
    for (int i = 0; i < 8; i++)
#pragma unroll
        for (int j = 0; j < 4; j++) accp[i][j] = 0ull;

    for (int st = s0; st < send; st += 16) {
        __syncthreads();
        for (int i = t; i < 800; i += 640) {
            int r = i / 50, c4 = i - (i / 50) * 50;
            int s = st + r;
            float4 qv = make_float4(0.f, 0.f, 0.f, 0.f), kv = qv;
            if (s < send && c4 < 49) {
                qv = *(const float4*)(Q + (size_t)s * 196 + c4 * 4);
                kv = *(const float4*)(K + (size_t)s * 196 + c4 * 4);
            }
            *(float4*)&ks[r][c4 * 4] = kv;
            *(float4*)&qsD[r][c4 * 8]     = make_float4(qv.x, qv.x, qv.y, qv.y);
            *(float4*)&qsD[r][c4 * 8 + 4] = make_float4(qv.z, qv.z, qv.w, qv.w);
        }
        __syncthreads();
        if (t < 625) {
#pragma unroll 2
            for (int ss = 0; ss < 16; ss++) {
                const u64* qd = (const u64*)&qsD[ss][ty * 16];
                const u64* kp = (const u64*)&ks[ss][tx * 8];
                u64 b0 = kp[0], b1 = kp[1], b2 = kp[2], b3 = kp[3];
#pragma unroll
                for (int i = 0; i < 8; i++) {
                    u64 ai = qd[i];
                    accp[i][0] = fma2(ai, b0, accp[i][0]);
                    accp[i][1] = fma2(ai, b1, accp[i][1]);
                    accp[i][2] = fma2(ai, b2, accp[i][2]);
                    accp[i][3] = fma2(ai, b3, accp[i][3]);
                }
            }
        }
    }
    if (t < 625) {
        float* out = g_wmp + ((size_t)b * GRIDK + kb) * (P2 * P2);
#pragma unroll
        for (int i = 0; i < 8; i++) {
            int p = ty * 8 + i;
            if (p < 196) {
#pragma unroll
                for (int jp = 0; jp < 4; jp++) {
                    float lo, hi;
                    unpack2(accp[i][jp], lo, hi);
                    int q = tx * 8 + jp * 2;
                    if (q < 196)     out[p * 196 + q]     = lo;
                    if (q + 1 < 196) out[p * 196 + q + 1] = hi;
                }
            }
        }
    }
}

// ---------------- K6: reduce wm partials + softmax + write padded wm^T ----------
__global__ void k_softmax_wm() {
    int b = blockIdx.y, p = blockIdx.x, t = threadIdx.x;
    __shared__ float red[256];
    float v = -3.0e38f;
    if (t < P2) {
        float s = 0.f;
        for (int r = 0; r < GRIDK; r++)
            s += g_wmp[((size_t)(b * GRIDK + r)) * (P2 * P2) + p * P2 + t];
        v = s * (1.f / 256.f);
    }
    red[t] = v;
    __syncthreads();
    for (int o = 128; o > 0; o >>= 1) {
        if (t < o) red[t] = fmaxf(red[t], red[t + o]);
        __syncthreads();
    }
    float mx = red[0];
    __syncthreads();
    float e = (t < P2) ? __expf(v - mx) : 0.f;
    red[t] = e;
    __syncthreads();
    for (int o = 128; o > 0; o >>= 1) {
        if (t < o) red[t] += red[t + o];
        __syncthreads();
    }
    float inv = 1.f / red[0];
    if (t < P2) g_wmT[(b * P2 + t) * P2P + p] = e * inv;
}

// ---------------- K7: wg[p][q] = qg[p].kg[q]/8 ----------------
__global__ __launch_bounds__(256) void k_wg() {
    int b = blockIdx.z;
    int p0 = blockIdx.y * 64, q0 = blockIdx.x * 64;
    __shared__ __align__(16) float Qs[64][64];
    __shared__ __align__(16) float Ks[64][64];
    const float* Qg = g_qg + (size_t)b * TG2 * CC;
    const float* Kg = g_kg + (size_t)b * TG2 * CC;
    int t = threadIdx.x;
    for (int i = t; i < 1024; i += 256) {
        int r = i >> 4, c4 = i & 15;
        float4 q4 = *(const float4*)(Qg + (p0 + r) * 64 + c4 * 4);
        float4 k4 = *(const float4*)(Kg + (q0 + r) * 64 + c4 * 4);
        Qs[c4 * 4 + 0][r] = q4.x; Qs[c4 * 4 + 1][r] = q4.y;
        Qs[c4 * 4 + 2][r] = q4.z; Qs[c4 * 4 + 3][r] = q4.w;
        Ks[c4 * 4 + 0][r] = k4.x; Ks[c4 * 4 + 1][r] = k4.y;
        Ks[c4 * 4 + 2][r] = k4.z; Ks[c4 * 4 + 3][r] = k4.w;
    }
    __syncthreads();
    int ty = t >> 4, tx = t & 15;
    float acc[4][4];
#pragma unroll
    for (int i = 0; i < 4; i++)
#pragma unroll
        for (int j = 0; j < 4; j++) acc[i][j] = 0.f;
#pragma unroll 8
    for (int c = 0; c < 64; c++) {
        float4 a4 = *(const float4*)&Qs[c][ty * 4];
        float4 b4 = *(const float4*)&Ks[c][tx * 4];
        float a[4] = {a4.x, a4.y, a4.z, a4.w};
        float bb[4] = {b4.x, b4.y, b4.z, b4.w};
#pragma unroll
        for (int i = 0; i < 4; i++)
#pragma unroll
            for (int j = 0; j < 4; j++) acc[i][j] += a[i] * bb[j];
    }
    float* out = g_wg + (size_t)b * TG2 * TG2;
#pragma unroll
    for (int i = 0; i < 4; i++) {
        float4 r = make_float4(acc[i][0] * 0.125f, acc[i][1] * 0.125f,
                               acc[i][2] * 0.125f, acc[i][3] * 0.125f);
        *(float4*)(out + (size_t)(p0 + ty * 4 + i) * TG2 + q0 + tx * 4) = r;
    }
}

// ---------------- K8: softmax over wg rows ----------------
__global__ void k_softmax_wg() {
    int b = blockIdx.y, p = blockIdx.x, t = threadIdx.x;
    float* row = g_wg + ((size_t)b * TG2 + p) * TG2;
    __shared__ __align__(16) float sv[TG2];
    __shared__ float red[256];
    float lm = -3.0e38f;
    for (int i = t; i < 784; i += 256) {
        float4 v = *(const float4*)(row + i * 4);
        *(float4*)(sv + i * 4) = v;
        lm = fmaxf(lm, fmaxf(fmaxf(v.x, v.y), fmaxf(v.z, v.w)));
    }
    red[t] = lm;
    __syncthreads();
    for (int o = 128; o > 0; o >>= 1) {
        if (t < o) red[t] = fmaxf(red[t], red[t + o]);
        __syncthreads();
    }
    float mx = red[0];
    __syncthreads();
    float ls = 0.f;
    for (int i = t; i < 784; i += 256) {
        float4 v = *(const float4*)(sv + i * 4);
        v.x = __expf(v.x - mx); v.y = __expf(v.y - mx);
        v.z = __expf(v.z - mx); v.w = __expf(v.w - mx);
        *(float4*)(sv + i * 4) = v;
        ls += v.x + v.y + v.z + v.w;
    }
    red[t] = ls;
    __syncthreads();
    for (int o = 128; o > 0; o >>= 1) {
        if (t < o) red[t] += red[t + o];
        __syncthreads();
    }
    float inv = 1.f / red[0];
    for (int i = t; i < 784; i += 256) {
        float4 v = *(const float4*)(sv + i * 4);
        v.x *= inv; v.y *= inv; v.z *= inv; v.w *= inv;
        *(float4*)(row + i * 4) = v;
    }
}

// ---------------- K9: hg[q][c] = sum_k wg[q][k]*vg[k][c] ----------------
__global__ __launch_bounds__(256) void k_hg() {
    int b = blockIdx.y;
    int q0 = blockIdx.x * 64;
    __shared__ __align__(16) float Ws[32][64];
    __shared__ __align__(16) float Vs[32][64];
    const float* Wg = g_wg + (size_t)b * TG2 * TG2;
    const float* Vg = g_vg + (size_t)b * TG2 * CC;
    int t = threadIdx.x;
    int ty = t >> 4, tx = t & 15;
    float acc[4][4];
#pragma unroll
    for (int i = 0; i < 4; i++)
#pragma unroll
        for (int j = 0; j < 4; j++) acc[i][j] = 0.f;

    for (int k0 = 0; k0 < TG2; k0 += 32) {
        __syncthreads();
        for (int i = t; i < 512; i += 256) {
            int r = i >> 3, k4 = i & 7;
            float4 w4 = *(const float4*)(Wg + (size_t)(q0 + r) * TG2 + k0 + k4 * 4);
            Ws[k4 * 4 + 0][r] = w4.x; Ws[k4 * 4 + 1][r] = w4.y;
            Ws[k4 * 4 + 2][r] = w4.z; Ws[k4 * 4 + 3][r] = w4.w;
        }
        for (int i = t; i < 512; i += 256) {
            int kk = i >> 4, c4 = i & 15;
            *(float4*)&Vs[kk][c4 * 4] = *(const float4*)(Vg + (k0 + kk) * 64 + c4 * 4);
        }
        __syncthreads();
#pragma unroll 8
        for (int kk = 0; kk < 32; kk++) {
            float4 a4 = *(const float4*)&Ws[kk][ty * 4];
            float4 b4 = *(const float4*)&Vs[kk][tx * 4];
            float a[4] = {a4.x, a4.y, a4.z, a4.w};
            float bb[4] = {b4.x, b4.y, b4.z, b4.w};
#pragma unroll
            for (int i = 0; i < 4; i++)
#pragma unroll
                for (int j = 0; j < 4; j++) acc[i][j] += a[i] * bb[j];
        }
    }
#pragma unroll
    for (int i = 0; i < 4; i++)
        *(float4*)(g_hg + (size_t)(b * TG2 + q0 + ty * 4 + i) * 64 + tx * 4) =
            make_float4(acc[i][0], acc[i][1], acc[i][2], acc[i][3]);
}

// ---------------- K10: hp[s][q] = sum_k v[s][k]*wmT[k][q], 8x8, FFMA2 ----------
__global__ __launch_bounds__(224) void k_hp() {
    int b = blockIdx.y;
    int s0 = blockIdx.x * 64;
    __shared__ __align__(16) float AsD[28][132];   // duplicated {v,v}, padded row
    __shared__ __align__(16) float Bs[28][200];
    const float* V   = g_v   + (size_t)b * NPB;
    const float* WMT = g_wmT + (size_t)b * (P2 * P2P);
    int t = threadIdx.x;
    int rg = t / 25, cg = t - (t / 25) * 25;       // workers t<200: 8x25 grid of 8x8 tiles
    u64 accp[8][4];
#pragma unroll
    for (int i = 0; i < 8; i++)
#pragma unroll
        for (int j = 0; j < 4; j++) accp[i][j] = 0ull;

    for (int k0 = 0; k0 < 196; k0 += 28) {
        __syncthreads();
        for (int i = t; i < 448; i += 224) {
            int r = i / 7, k4 = i - (i / 7) * 7;
            float4 vv = *(const float4*)(V + (size_t)(s0 + r) * 196 + k0 + k4 * 4);
            *(float2*)&AsD[k4 * 4 + 0][2 * r] = make_float2(vv.x, vv.x);
            *(float2*)&AsD[k4 * 4 + 1][2 * r] = make_float2(vv.y, vv.y);
            *(float2*)&AsD[k4 * 4 + 2][2 * r] = make_float2(vv.z, vv.z);
            *(float2*)&AsD[k4 * 4 + 3][2 * r] = make_float2(vv.w, vv.w);
        }
        for (int i = t; i < 1400; i += 224) {
            int r = i / 50, c4 = i - (i / 50) * 50;
            *(float4*)&Bs[r][c4 * 4] = *(const float4*)(WMT + (size_t)(k0 + r) * P2P + c4 * 4);
        }
        __syncthreads();
        if (t < 200) {
#pragma unroll 4
            for (int kk = 0; kk < 28; kk++) {
                const u64* ad = (const u64*)&AsD[kk][rg * 16];
                const u64* bp = (const u64*)&Bs[kk][cg * 8];
                u64 b0 = bp[0], b1 = bp[1], b2 = bp[2], b3 = bp[3];
#pragma unroll
                for (int i = 0; i < 8; i++) {
                    u64 ai = ad[i];
                    accp[i][0] = fma2(ai, b0, accp[i][0]);
                    accp[i][1] = fma2(ai, b1, accp[i][1]);
                    accp[i][2] = fma2(ai, b2, accp[i][2]);
                    accp[i][3] = fma2(ai, b3, accp[i][3]);
                }
            }
        }
    }
    if (t < 200) {
        float* O = g_hin + (size_t)b * NPB;
#pragma unroll
        for (int i = 0; i < 8; i++) {
            size_t row = (size_t)(s0 + rg * 8 + i) * 196;
#pragma unroll
            for (int jp = 0; jp < 4; jp++) {
                float lo, hi;
                unpack2(accp[i][jp], lo, hi);
                int q = cg * 8 + jp * 2;
                if (q < 196)     O[row + q]     = lo;
                if (q + 1 < 196) O[row + q + 1] = hi;
            }
        }
    }
}

// ---------------- K11: proj fused blend + conv + residual, FFMA2 ----------------
__global__ __launch_bounds__(128) void k_proj(const float* __restrict__ x,
                                              const float* __restrict__ pw,
                                              float* __restrict__ out) {
    __shared__ __align__(16) float sH[64][128];
    __shared__ __align__(16) float sWt[64][64];
    int b = blockIdx.y;
    int pix0 = blockIdx.x * 128;
    int t = threadIdx.x;

    for (int i = t; i < 2048; i += 128) {
        int c = i >> 5, p4 = i & 31;
        int pgl = pix0 + p4 * 4;
        int h = pgl / WID, w = pgl - h * WID;
        int cell = (h >> 3) * 56 + (w >> 3);
        float4 hp = *(const float4*)(g_hin + (size_t)b * NPB + (size_t)c * HW + pgl);
        float hg = g_hg[(size_t)(b * TG2 + cell) * 64 + c] * 0.25f;
        float4 r = make_float4(0.75f * hp.x + hg, 0.75f * hp.y + hg,
                               0.75f * hp.z + hg, 0.75f * hp.w + hg);
        *(float4*)&sH[c][p4 * 4] = r;
    }
    for (int i = t; i < 1024; i += 128) {
        int o = i & 63, c4 = i >> 6;
        float4 w = *(const float4*)(pw + o * 64 + c4 * 4);
        sWt[c4 * 4 + 0][o] = w.x;
        sWt[c4 * 4 + 1][o] = w.y;
        sWt[c4 * 4 + 2][o] = w.z;
        sWt[c4 * 4 + 3][o] = w.w;
    }
    __syncthreads();

    int og = t >> 4, pg = t & 15;
    u64 accp[8][4];
#pragma unroll
    for (int i = 0; i < 8; i++)
#pragma unroll
        for (int j = 0; j < 4; j++) accp[i][j] = 0ull;

#pragma unroll 8
    for (int c = 0; c < 64; c++) {
        const u64* xp = (const u64*)&sH[c][pg * 4];
        const u64* xq = (const u64*)&sH[c][pg * 4 + 64];
        u64 x0 = xp[0], x1 = xp[1], x2 = xq[0], x3 = xq[1];
        float4 w0 = *(const float4*)&sWt[c][og * 4];
        float4 w1 = *(const float4*)&sWt[c][og * 4 + 32];
        float aw[8] = {w0.x, w0.y, w0.z, w0.w, w1.x, w1.y, w1.z, w1.w};
#pragma unroll
        for (int i = 0; i < 8; i++) {
            u64 ad = pack2(aw[i], aw[i]);
            accp[i][0] = fma2(ad, x0, accp[i][0]);
            accp[i][1] = fma2(ad, x1, accp[i][1]);
            accp[i][2] = fma2(ad, x2, accp[i][2]);
            accp[i][3] = fma2(ad, x3, accp[i][3]);
        }
    }
#pragma unroll
    for (int i = 0; i < 8; i++) {
        int o = og * 4 + ((i < 4) ? i : 28 + i);
        size_t base = ((size_t)b * CC + o) * HW + pix0;
        float4 xr0 = *(const float4*)(x + base + pg * 4);
        float4 xr1 = *(const float4*)(x + base + 64 + pg * 4);
        float l0, h0, l1, h1;
        unpack2(accp[i][0], l0, h0); unpack2(accp[i][1], l1, h1);
        *(float4*)(out + base + pg * 4) =
            make_float4(l0 + xr0.x, h0 + xr0.y, l1 + xr0.z, h1 + xr0.w);
        unpack2(accp[i][2], l0, h0); unpack2(accp[i][3], l1, h1);
        *(float4*)(out + base + 64 + pg * 4) =
            make_float4(l0 + xr1.x, h0 + xr1.y, l1 + xr1.z, h1 + xr1.w);
    }
}

extern "C" void kernel_launch(void* const* d_in, const int* in_sizes, int n_in,
                              void* d_out, int out_size) {
    const float* x   = (const float*)d_in[0];
    const float* gnw = (const float*)d_in[1];
    const float* gnb = (const float*)d_in[2];
    const float* qw  = (const float*)d_in[3];
    const float* qb  = (const float*)d_in[4];
    const float* kw  = (const float*)d_in[5];
    const float* kb  = (const float*)d_in[6];
    const float* vw  = (const float*)d_in[7];
    const float* vb  = (const float*)d_in[8];
    const float* pw  = (const float*)d_in[9];
    float* out = (float*)d_out;

    k_pool_stats<<<dim3(784, BATCH), 256>>>(x);
    k_stats2<<<BATCH, 256>>>();
    k_qkvg<<<dim3(TG2, BATCH), 64>>>(gnw, gnb, qw, qb, kw, kb, vw, vb);
    k_qkv<<<dim3(HW / 128, BATCH), 128>>>(x, gnw, gnb, qw, qb, kw, kb, vw, vb);
    k_wm<<<dim3(GRIDK, BATCH), 640>>>();
    k_softmax_wm<<<dim3(P2, BATCH), 256>>>();
    k_wg<<<dim3(TG2 / 64, TG2 / 64, BATCH), 256>>>();
    k_softmax_wg<<<dim3(TG2, BATCH), 256>>>();
    k_hg<<<dim3(TG2 / 64, BATCH), 256>>>();
    k_hp<<<dim3(SPB / 64, BATCH), 224>>>();
    k_proj<<<dim3(HW / 128, BATCH), 128>>>(x, pw, out);
}

// round 9
// speedup vs baseline: 1.0548x; 1.0548x over previous
#include <cuda_runtime.h>

#define HW      200704          // 448*448
#define WID     448
#define CC      64
#define BATCH   2
#define TG2     3136            // 56*56
#define P2      196
#define P2P     200             // padded q-dim (pads stay zero: device globals are zero-init)
#define NPB     12845056        // C*HW per batch
#define SPB     65536           // S per batch
#define EPSV    1e-5f
#define GRIDK   74
#define KCHUNK  886             // ceil(65536/74)

typedef unsigned long long u64;
__device__ __forceinline__ u64 pack2(float lo, float hi) {
    u64 r; asm("mov.b64 %0,{%1,%2};" : "=l"(r) : "f"(lo), "f"(hi)); return r;
}
__device__ __forceinline__ void unpack2(u64 v, float& lo, float& hi) {
    asm("mov.b64 {%0,%1},%2;" : "=f"(lo), "=f"(hi) : "l"(v));
}
__device__ __forceinline__ u64 fma2(u64 a, u64 b, u64 c) {
    u64 d; asm("fma.rn.f32x2 %0,%1,%2,%3;" : "=l"(d) : "l"(a), "l"(b), "l"(c)); return d;
}

// ---- tf32 MMA helpers ----
__device__ __forceinline__ unsigned f2tf(float x) {
    unsigned r; asm("cvt.rna.tf32.f32 %0,%1;" : "=r"(r) : "f"(x)); return r;
}
__device__ __forceinline__ void split2(float x, unsigned& h, unsigned& l) {
    h = f2tf(x);
    l = f2tf(x - __uint_as_float(h));
}
__device__ __forceinline__ void mma_tf32(float* c, unsigned a0, unsigned a1, unsigned a2, unsigned a3,
                                         unsigned b0, unsigned b1) {
    asm volatile("mma.sync.aligned.m16n8k8.row.col.f32.tf32.tf32.f32 "
                 "{%0,%1,%2,%3},{%4,%5,%6,%7},{%8,%9},{%0,%1,%2,%3};"
                 : "+f"(c[0]), "+f"(c[1]), "+f"(c[2]), "+f"(c[3])
                 : "r"(a0), "r"(a1), "r"(a2), "r"(a3), "r"(b0), "r"(b1));
}

// ---------------- scratch ----------------
__device__ float g_q[BATCH * NPB];
__device__ float g_k[BATCH * NPB];
__device__ float g_v[BATCH * NPB];
__device__ float g_hin[BATCH * NPB];
__device__ float g_spart[BATCH * 784 * 2];
__device__ float g_stats[BATCH * 2];
__device__ float g_px[BATCH * CC * TG2];
__device__ float g_qg[BATCH * TG2 * CC];
__device__ float g_kg[BATCH * TG2 * CC];
__device__ float g_vg[BATCH * TG2 * CC];
__device__ float g_wmp[BATCH * GRIDK * P2 * P2];
__device__ float g_wmT[BATCH * P2 * P2P];    // wmT[k][q], q padded to 200 (pads never written -> 0)
__device__ float g_wg[(size_t)BATCH * TG2 * TG2];
__device__ float g_hg[BATCH * TG2 * CC];

// ---------------- K1: 8x8 avg-pool of x + GN stat partials ----------------
__global__ __launch_bounds__(256) void k_pool_stats(const float* __restrict__ x) {
    int b = blockIdx.y;
    int idx = blockIdx.x * 256 + threadIdx.x;
    int c = idx / TG2;
    int cell = idx - c * TG2;
    int th = cell / 56, tw = cell - th * 56;
    const float* xp = x + ((size_t)b * CC + c) * HW + (size_t)(th * 8) * WID + tw * 8;
    float s = 0.f, s2 = 0.f;
#pragma unroll
    for (int r = 0; r < 8; r++) {
        float4 a = *(const float4*)(xp + r * WID);
        float4 bb = *(const float4*)(xp + r * WID + 4);
        s  += a.x + a.y + a.z + a.w + bb.x + bb.y + bb.z + bb.w;
        s2 += a.x*a.x + a.y*a.y + a.z*a.z + a.w*a.w
            + bb.x*bb.x + bb.y*bb.y + bb.z*bb.z + bb.w*bb.w;
    }
    g_px[(b * CC + c) * TG2 + cell] = s * (1.f / 64.f);

    __shared__ float r0[256], r1[256];
    int t = threadIdx.x;
    r0[t] = s; r1[t] = s2;
    __syncthreads();
    for (int o = 128; o > 0; o >>= 1) {
        if (t < o) { r0[t] += r0[t + o]; r1[t] += r1[t + o]; }
        __syncthreads();
    }
    if (t == 0) {
        g_spart[(b * 784 + blockIdx.x) * 2 + 0] = r0[0];
        g_spart[(b * 784 + blockIdx.x) * 2 + 1] = r1[0];
    }
}

// ---------------- K2: reduce stat partials ----------------
__global__ void k_stats2() {
    int b = blockIdx.x, t = threadIdx.x;
    float s = 0.f, s2 = 0.f;
    for (int i = t; i < 784; i += 256) {
        s  += g_spart[(b * 784 + i) * 2 + 0];
        s2 += g_spart[(b * 784 + i) * 2 + 1];
    }
    __shared__ float r0[256], r1[256];
    r0[t] = s; r1[t] = s2;
    __syncthreads();
    for (int o = 128; o > 0; o >>= 1) {
        if (t < o) { r0[t] += r0[t + o]; r1[t] += r1[t + o]; }
        __syncthreads();
    }
    if (t == 0) { g_stats[b * 2] = r0[0]; g_stats[b * 2 + 1] = r1[0]; }
}

// ---------------- K3: pooled qkv from pooled x ----------------
__global__ void k_qkvg(const float* __restrict__ gnw, const float* __restrict__ gnb,
                       const float* __restrict__ qw, const float* __restrict__ qb,
                       const float* __restrict__ kw, const float* __restrict__ kb,
                       const float* __restrict__ vw, const float* __restrict__ vb) {
    int b = blockIdx.y, cell = blockIdx.x, o = threadIdx.x;
    float mean = g_stats[b * 2] * (1.f / (float)NPB);
    float var  = g_stats[b * 2 + 1] * (1.f / (float)NPB) - mean * mean;
    float inv  = rsqrtf(var + EPSV);
    __shared__ float xn[64];
    xn[o] = (g_px[(b * CC + o) * TG2 + cell] - mean) * inv * gnw[o] + gnb[o];
    __syncthreads();
    float aq = qb[o], ak = kb[o], av = vb[o];
#pragma unroll 8
    for (int j = 0; j < 64; j++) {
        float xv = xn[j];
        aq += qw[o * 64 + j] * xv;
        ak += kw[o * 64 + j] * xv;
        av += vw[o * 64 + j] * xv;
    }
    int off = (b * TG2 + cell) * CC + o;
    g_qg[off] = aq; g_kg[off] = ak; g_vg[off] = av;
}

// ---------------- K4: GN + q/k/v convs, 8x8 tiles, FFMA2 inner ----------------
__global__ __launch_bounds__(128) void k_qkv(const float* __restrict__ x,
                                             const float* __restrict__ gnw, const float* __restrict__ gnb,
                                             const float* __restrict__ W0, const float* __restrict__ B0,
                                             const float* __restrict__ W1, const float* __restrict__ B1,
                                             const float* __restrict__ W2, const float* __restrict__ B2) {
    __shared__ __align__(16) float sXn[64][128];
    __shared__ __align__(16) float sWt[64][64];
    __shared__ float sB[64];
    int b = blockIdx.y;
    int pix0 = blockIdx.x * 128;
    int t = threadIdx.x;
    float mean = g_stats[b * 2] * (1.f / (float)NPB);
    float inv  = rsqrtf(g_stats[b * 2 + 1] * (1.f / (float)NPB) - mean * mean + EPSV);

    for (int i = t; i < 2048; i += 128) {
        int c = i >> 5, p4 = i & 31;
        float4 v = *(const float4*)(x + ((size_t)b * CC + c) * HW + pix0 + p4 * 4);
        float gw = gnw[c] * inv, gb = gnb[c] - mean * gnw[c] * inv;
        v.x = v.x * gw + gb; v.y = v.y * gw + gb;
        v.z = v.z * gw + gb; v.w = v.w * gw + gb;
        *(float4*)&sXn[c][p4 * 4] = v;
    }
    const float* Ws[3] = {W0, W1, W2};
    const float* Bs[3] = {B0, B1, B2};
    float* Os[3] = {g_q, g_k, g_v};
    int og = t >> 4, pg = t & 15;

    for (int m = 0; m < 3; m++) {
        __syncthreads();
        for (int i = t; i < 1024; i += 128) {
            int o = i & 63, c4 = i >> 6;
            float4 w = *(const float4*)(Ws[m] + o * 64 + c4 * 4);
            sWt[c4 * 4 + 0][o] = w.x;
            sWt[c4 * 4 + 1][o] = w.y;
            sWt[c4 * 4 + 2][o] = w.z;
            sWt[c4 * 4 + 3][o] = w.w;
        }
        if (t < 64) sB[t] = Bs[m][t];
        __syncthreads();

        u64 accp[8][4];
#pragma unroll
        for (int i = 0; i < 8; i++) {
            int o = og * 4 + ((i < 4) ? i : 28 + i);
            u64 bp = pack2(sB[o], sB[o]);
            accp[i][0] = bp; accp[i][1] = bp; accp[i][2] = bp; accp[i][3] = bp;
        }
#pragma unroll 8
        for (int c = 0; c < 64; c++) {
            const u64* xp = (const u64*)&sXn[c][pg * 4];
            const u64* xq = (const u64*)&sXn[c][pg * 4 + 64];
            u64 x0 = xp[0], x1 = xp[1], x2 = xq[0], x3 = xq[1];
            float4 w0 = *(const float4*)&sWt[c][og * 4];
            float4 w1 = *(const float4*)&sWt[c][og * 4 + 32];
            float aw[8] = {w0.x, w0.y, w0.z, w0.w, w1.x, w1.y, w1.z, w1.w};
#pragma unroll
            for (int i = 0; i < 8; i++) {
                u64 ad = pack2(aw[i], aw[i]);
                accp[i][0] = fma2(ad, x0, accp[i][0]);
                accp[i][1] = fma2(ad, x1, accp[i][1]);
                accp[i][2] = fma2(ad, x2, accp[i][2]);
                accp[i][3] = fma2(ad, x3, accp[i][3]);
            }
        }
        float* O = Os[m];
#pragma unroll
        for (int i = 0; i < 8; i++) {
            int o = og * 4 + ((i < 4) ? i : 28 + i);
            size_t base = ((size_t)b * CC + o) * HW + pix0;
            float l0, h0, l1, h1;
            unpack2(accp[i][0], l0, h0); unpack2(accp[i][1], l1, h1);
            *(float4*)(O + base + pg * 4) = make_float4(l0, h0, l1, h1);
            unpack2(accp[i][2], l0, h0); unpack2(accp[i][3], l1, h1);
            *(float4*)(O + base + 64 + pg * 4) = make_float4(l0, h0, l1, h1);
        }
    }
}

// ---------------- K5: wm split-K GEMM on tensor cores (3xTF32) ----------------
// wm[p][q] = sum_s Q[s][p]*K[s][q].  A[m=p][k=s] = Q[s][p] (rows of Q ARE p-contiguous).
#define WSTR 216    // 216 % 32 == 24 -> conflict-free frag loads
__global__ __launch_bounds__(416, 1) void k_wm() {
    int b = blockIdx.y, kb = blockIdx.x;
    int s0 = kb * KCHUNK, send = min(s0 + KCHUNK, SPB);
    const float* Q = g_q + (size_t)b * NPB;
    const float* K = g_k + (size_t)b * NPB;
    __shared__ __align__(16) float Aq[8][WSTR];
    __shared__ __align__(16) float Kb[8][WSTR];
    int t = threadIdx.x;
    for (int i = t; i < 8 * WSTR; i += 416) { ((float*)Aq)[i] = 0.f; ((float*)Kb)[i] = 0.f; }
    int lane = t & 31, w = t >> 5;          // 13 warps
    int gid = lane >> 2, tig = lane & 3;
    int m0 = w * 16;
    float acc[25][4];
#pragma unroll
    for (int nt = 0; nt < 25; nt++) { acc[nt][0] = acc[nt][1] = acc[nt][2] = acc[nt][3] = 0.f; }

    for (int st = s0; st < send; st += 8) {
        __syncthreads();
        if (t < 392) {                       // 8 rows x 49 float4 each
            int r = t / 49, c4 = t - (t / 49) * 49;
            int s = st + r;
            float4 qv = make_float4(0.f, 0.f, 0.f, 0.f), kv = qv;
            if (s < send) {
                qv = *(const float4*)(Q + (size_t)s * 196 + c4 * 4);
                kv = *(const float4*)(K + (size_t)s * 196 + c4 * 4);
            }
            *(float4*)&Aq[r][c4 * 4] = qv;
            *(float4*)&Kb[r][c4 * 4] = kv;
        }
        __syncthreads();
        unsigned ah[4], al[4];
        split2(Aq[tig    ][m0 + gid    ], ah[0], al[0]);
        split2(Aq[tig    ][m0 + gid + 8], ah[1], al[1]);
        split2(Aq[tig + 4][m0 + gid    ], ah[2], al[2]);
        split2(Aq[tig + 4][m0 + gid + 8], ah[3], al[3]);
#pragma unroll
        for (int nt = 0; nt < 25; nt++) {
            int n0 = nt * 8;
            unsigned bh0, bl0, bh1, bl1;
            split2(Kb[tig    ][n0 + gid], bh0, bl0);
            split2(Kb[tig + 4][n0 + gid], bh1, bl1);
            mma_tf32(acc[nt], ah[0], ah[1], ah[2], ah[3], bh0, bh1);
            mma_tf32(acc[nt], ah[0], ah[1], ah[2], ah[3], bl0, bl1);
            mma_tf32(acc[nt], al[0], al[1], al[2], al[3], bh0, bh1);
        }
    }
    float* out = g_wmp + ((size_t)b * GRIDK + kb) * (P2 * P2);
    int p0 = m0 + gid, p1 = p0 + 8;
#pragma unroll
    for (int nt = 0; nt < 25; nt++) {
        int q0 = nt * 8 + 2 * tig;
        if (p0 < 196) {
            if (q0 < 196)     out[p0 * 196 + q0]     = acc[nt][0];
            if (q0 + 1 < 196) out[p0 * 196 + q0 + 1] = acc[nt][1];
        }
        if (p1 < 196) {
            if (q0 < 196)     out[p1 * 196 + q0]     = acc[nt][2];
            if (q0 + 1 < 196) out[p1 * 196 + q0 + 1] = acc[nt][3];
        }
    }
}

// ---------------- K6: reduce wm partials + softmax + write padded wm^T ----------
__global__ void k_softmax_wm() {
    int b = blockIdx.y, p = blockIdx.x, t = threadIdx.x;
    __shared__ float red[256];
    float v = -3.0e38f;
    if (t < P2) {
        float s = 0.f;
        for (int r = 0; r < GRIDK; r++)
            s += g_wmp[((size_t)(b * GRIDK + r)) * (P2 * P2) + p * P2 + t];
        v = s * (1.f / 256.f);
    }
    red[t] = v;
    __syncthreads();
    for (int o = 128; o > 0; o >>= 1) {
        if (t < o) red[t] = fmaxf(red[t], red[t + o]);
        __syncthreads();
    }
    float mx = red[0];
    __syncthreads();
    float e = (t < P2) ? __expf(v - mx) : 0.f;
    red[t] = e;
    __syncthreads();
    for (int o = 128; o > 0; o >>= 1) {
        if (t < o) red[t] += red[t + o];
        __syncthreads();
    }
    float inv = 1.f / red[0];
    if (t < P2) g_wmT[(b * P2 + t) * P2P + p] = e * inv;
}

// ---------------- K7: wg[p][q] = qg[p].kg[q]/8 ----------------
__global__ __launch_bounds__(256) void k_wg() {
    int b = blockIdx.z;
    int p0 = blockIdx.y * 64, q0 = blockIdx.x * 64;
    __shared__ __align__(16) float Qs[64][64];
    __shared__ __align__(16) float Ks[64][64];
    const float* Qg = g_qg + (size_t)b * TG2 * CC;
    const float* Kg = g_kg + (size_t)b * TG2 * CC;
    int t = threadIdx.x;
    for (int i = t; i < 1024; i += 256) {
        int r = i >> 4, c4 = i & 15;
        float4 q4 = *(const float4*)(Qg + (p0 + r) * 64 + c4 * 4);
        float4 k4 = *(const float4*)(Kg + (q0 + r) * 64 + c4 * 4);
        Qs[c4 * 4 + 0][r] = q4.x; Qs[c4 * 4 + 1][r] = q4.y;
        Qs[c4 * 4 + 2][r] = q4.z; Qs[c4 * 4 + 3][r] = q4.w;
        Ks[c4 * 4 + 0][r] = k4.x; Ks[c4 * 4 + 1][r] = k4.y;
        Ks[c4 * 4 + 2][r] = k4.z; Ks[c4 * 4 + 3][r] = k4.w;
    }
    __syncthreads();
    int ty = t >> 4, tx = t & 15;
    float acc[4][4];
#pragma unroll
    for (int i = 0; i < 4; i++)
#pragma unroll
        for (int j = 0; j < 4; j++) acc[i][j] = 0.f;
#pragma unroll 8
    for (int c = 0; c < 64; c++) {
        float4 a4 = *(const float4*)&Qs[c][ty * 4];
        float4 b4 = *(const float4*)&Ks[c][tx * 4];
        float a[4] = {a4.x, a4.y, a4.z, a4.w};
        float bb[4] = {b4.x, b4.y, b4.z, b4.w};
#pragma unroll
        for (int i = 0; i < 4; i++)
#pragma unroll
            for (int j = 0; j < 4; j++) acc[i][j] += a[i] * bb[j];
    }
    float* out = g_wg + (size_t)b * TG2 * TG2;
#pragma unroll
    for (int i = 0; i < 4; i++) {
        float4 r = make_float4(acc[i][0] * 0.125f, acc[i][1] * 0.125f,
                               acc[i][2] * 0.125f, acc[i][3] * 0.125f);
        *(float4*)(out + (size_t)(p0 + ty * 4 + i) * TG2 + q0 + tx * 4) = r;
    }
}

// ---------------- K8: softmax over wg rows ----------------
__global__ void k_softmax_wg() {
    int b = blockIdx.y, p = blockIdx.x, t = threadIdx.x;
    float* row = g_wg + ((size_t)b * TG2 + p) * TG2;
    __shared__ __align__(16) float sv[TG2];
    __shared__ float red[256];
    float lm = -3.0e38f;
    for (int i = t; i < 784; i += 256) {
        float4 v = *(const float4*)(row + i * 4);
        *(float4*)(sv + i * 4) = v;
        lm = fmaxf(lm, fmaxf(fmaxf(v.x, v.y), fmaxf(v.z, v.w)));
    }
    red[t] = lm;
    __syncthreads();
    for (int o = 128; o > 0; o >>= 1) {
        if (t < o) red[t] = fmaxf(red[t], red[t + o]);
        __syncthreads();
    }
    float mx = red[0];
    __syncthreads();
    float ls = 0.f;
    for (int i = t; i < 784; i += 256) {
        float4 v = *(const float4*)(sv + i * 4);
        v.x = __expf(v.x - mx); v.y = __expf(v.y - mx);
        v.z = __expf(v.z - mx); v.w = __expf(v.w - mx);
        *(float4*)(sv + i * 4) = v;
        ls += v.x + v.y + v.z + v.w;
    }
    red[t] = ls;
    __syncthreads();
    for (int o = 128; o > 0; o >>= 1) {
        if (t < o) red[t] += red[t + o];
        __syncthreads();
    }
    float inv = 1.f / red[0];
    for (int i = t; i < 784; i += 256) {
        float4 v = *(const float4*)(sv + i * 4);
        v.x *= inv; v.y *= inv; v.z *= inv; v.w *= inv;
        *(float4*)(row + i * 4) = v;
    }
}

// ---------------- K9: hg[q][c] = sum_k wg[q][k]*vg[k][c] ----------------
__global__ __launch_bounds__(256) void k_hg() {
    int b = blockIdx.y;
    int q0 = blockIdx.x * 64;
    __shared__ __align__(16) float Ws[32][64];
    __shared__ __align__(16) float Vs[32][64];
    const float* Wg = g_wg + (size_t)b * TG2 * TG2;
    const float* Vg = g_vg + (size_t)b * TG2 * CC;
    int t = threadIdx.x;
    int ty = t >> 4, tx = t & 15;
    float acc[4][4];
#pragma unroll
    for (int i = 0; i < 4; i++)
#pragma unroll
        for (int j = 0; j < 4; j++) acc[i][j] = 0.f;

    for (int k0 = 0; k0 < TG2; k0 += 32) {
        __syncthreads();
        for (int i = t; i < 512; i += 256) {
            int r = i >> 3, k4 = i & 7;
            float4 w4 = *(const float4*)(Wg + (size_t)(q0 + r) * TG2 + k0 + k4 * 4);
            Ws[k4 * 4 + 0][r] = w4.x; Ws[k4 * 4 + 1][r] = w4.y;
            Ws[k4 * 4 + 2][r] = w4.z; Ws[k4 * 4 + 3][r] = w4.w;
        }
        for (int i = t; i < 512; i += 256) {
            int kk = i >> 4, c4 = i & 15;
            *(float4*)&Vs[kk][c4 * 4] = *(const float4*)(Vg + (k0 + kk) * 64 + c4 * 4);
        }
        __syncthreads();
#pragma unroll 8
        for (int kk = 0; kk < 32; kk++) {
            float4 a4 = *(const float4*)&Ws[kk][ty * 4];
            float4 b4 = *(const float4*)&Vs[kk][tx * 4];
            float a[4] = {a4.x, a4.y, a4.z, a4.w};
            float bb[4] = {b4.x, b4.y, b4.z, b4.w};
#pragma unroll
            for (int i = 0; i < 4; i++)
#pragma unroll
                for (int j = 0; j < 4; j++) acc[i][j] += a[i] * bb[j];
        }
    }
#pragma unroll
    for (int i = 0; i < 4; i++)
        *(float4*)(g_hg + (size_t)(b * TG2 + q0 + ty * 4 + i) * 64 + tx * 4) =
            make_float4(acc[i][0], acc[i][1], acc[i][2], acc[i][3]);
}

// ---------------- K10: hp = V * wm^T on tensor cores (3xTF32) ----------------
// hp[s][q] = sum_k V[s][k] * wmT[k][q].  M=65536 (128/block), N=200, K=196->200.
#define HASTR 136   // 136 % 32 == 8 -> conflict-free frag loads
#define HBSTR 216
__global__ __launch_bounds__(256, 1) void k_hp() {
    int b = blockIdx.y;
    int s0 = blockIdx.x * 128;
    const float* V = g_v + (size_t)b * NPB;
    const float* W = g_wmT + (size_t)b * (P2 * P2P);
    __shared__ __align__(16) float Av[8][HASTR];     // [k][m] (transposed V tile)
    __shared__ __align__(16) float Bw[8][HBSTR];     // [k][q]
    int t = threadIdx.x;
    int lane = t & 31, w = t >> 5;                   // 8 warps
    int gid = lane >> 2, tig = lane & 3;
    int m0 = w * 16;
    float acc[25][4];
#pragma unroll
    for (int nt = 0; nt < 25; nt++) { acc[nt][0] = acc[nt][1] = acc[nt][2] = acc[nt][3] = 0.f; }

    for (int k0 = 0; k0 < 200; k0 += 8) {
        __syncthreads();
        {   // V tile: 128 rows x 8 k-cols, one float4 per thread, transposed store
            int r = t >> 1, jj = t & 1;
            int kbase = k0 + jj * 4;
            float4 vv = make_float4(0.f, 0.f, 0.f, 0.f);
            if (kbase < 196) vv = *(const float4*)(V + (size_t)(s0 + r) * 196 + kbase);
            Av[jj * 4 + 0][r] = vv.x; Av[jj * 4 + 1][r] = vv.y;
            Av[jj * 4 + 2][r] = vv.z; Av[jj * 4 + 3][r] = vv.w;
        }
        for (int i = t; i < 400; i += 256) {         // 8 rows x 50 float4
            int r = i / 50, c4 = i - (i / 50) * 50;
            int kg = k0 + r;
            float4 wv = make_float4(0.f, 0.f, 0.f, 0.f);
            if (kg < 196) wv = *(const float4*)(W + (size_t)kg * P2P + c4 * 4);
            *(float4*)&Bw[r][c4 * 4] = wv;
        }
        __syncthreads();
        unsigned ah[4], al[4];
        split2(Av[tig    ][m0 + gid    ], ah[0], al[0]);
        split2(Av[tig    ][m0 + gid + 8], ah[1], al[1]);
        split2(Av[tig + 4][m0 + gid    ], ah[2], al[2]);
        split2(Av[tig + 4][m0 + gid + 8], ah[3], al[3]);
#pragma unroll
        for (int nt = 0; nt < 25; nt++) {
            int n0 = nt * 8;
            unsigned bh0, bl0, bh1, bl1;
            split2(Bw[tig    ][n0 + gid], bh0, bl0);
            split2(Bw[tig + 4][n0 + gid], bh1, bl1);
            mma_tf32(acc[nt], ah[0], ah[1], ah[2], ah[3], bh0, bh1);
            mma_tf32(acc[nt], ah[0], ah[1], ah[2], ah[3], bl0, bl1);
            mma_tf32(acc[nt], al[0], al[1], al[2], al[3], bh0, bh1);
        }
    }
    float* O = g_hin + (size_t)b * NPB;
    size_t r0 = (size_t)(s0 + m0 + gid) * 196;
    size_t r1 = r0 + 8 * 196;
#pragma unroll
    for (int nt = 0; nt < 25; nt++) {
        int q0 = nt * 8 + 2 * tig;
        if (q0 < 196) {
            O[r0 + q0] = acc[nt][0];
            O[r1 + q0] = acc[nt][2];
            if (q0 + 1 < 196) {
                O[r0 + q0 + 1] = acc[nt][1];
                O[r1 + q0 + 1] = acc[nt][3];
            }
        }
    }
}

// ---------------- K11: proj fused blend + conv + residual, FFMA2 ----------------
__global__ __launch_bounds__(128) void k_proj(const float* __restrict__ x,
                                              const float* __restrict__ pw,
                                              float* __restrict__ out) {
    __shared__ __align__(16) float sH[64][128];
    __shared__ __align__(16) float sWt[64][64];
    int b = blockIdx.y;
    int pix0 = blockIdx.x * 128;
    int t = threadIdx.x;

    for (int i = t; i < 2048; i += 128) {
        int c = i >> 5, p4 = i & 31;
        int pgl = pix0 + p4 * 4;
        int h = pgl / WID, w = pgl - h * WID;
        int cell = (h >> 3) * 56 + (w >> 3);
        float4 hp = *(const float4*)(g_hin + (size_t)b * NPB + (size_t)c * HW + pgl);
        float hg = g_hg[(size_t)(b * TG2 + cell) * 64 + c] * 0.25f;
        float4 r = make_float4(0.75f * hp.x + hg, 0.75f * hp.y + hg,
                               0.75f * hp.z + hg, 0.75f * hp.w + hg);
        *(float4*)&sH[c][p4 * 4] = r;
    }
    for (int i = t; i < 1024; i += 128) {
        int o = i & 63, c4 = i >> 6;
        float4 w = *(const float4*)(pw + o * 64 + c4 * 4);
        sWt[c4 * 4 + 0][o] = w.x;
        sWt[c4 * 4 + 1][o] = w.y;
        sWt[c4 * 4 + 2][o] = w.z;
        sWt[c4 * 4 + 3][o] = w.w;
    }
    __syncthreads();

    int og = t >> 4, pg = t & 15;
    u64 accp[8][4];
#pragma unroll
    for (int i = 0; i < 8; i++)
#pragma unroll
        for (int j = 0; j < 4; j++) accp[i][j] = 0ull;

#pragma unroll 8
    for (int c = 0; c < 64; c++) {
        const u64* xp = (const u64*)&sH[c][pg * 4];
        const u64* xq = (const u64*)&sH[c][pg * 4 + 64];
        u64 x0 = xp[0], x1 = xp[1], x2 = xq[0], x3 = xq[1];
        float4 w0 = *(const float4*)&sWt[c][og * 4];
        float4 w1 = *(const float4*)&sWt[c][og * 4 + 32];
        float aw[8] = {w0.x, w0.y, w0.z, w0.w, w1.x, w1.y, w1.z, w1.w};
#pragma unroll
        for (int i = 0; i < 8; i++) {
            u64 ad = pack2(aw[i], aw[i]);
            accp[i][0] = fma2(ad, x0, accp[i][0]);
            accp[i][1] = fma2(ad, x1, accp[i][1]);
            accp[i][2] = fma2(ad, x2, accp[i][2]);
            accp[i][3] = fma2(ad, x3, accp[i][3]);
        }
    }
#pragma unroll
    for (int i = 0; i < 8; i++) {
        int o = og * 4 + ((i < 4) ? i : 28 + i);
        size_t base = ((size_t)b * CC + o) * HW + pix0;
        float4 xr0 = *(const float4*)(x + base + pg * 4);
        float4 xr1 = *(const float4*)(x + base + 64 + pg * 4);
        float l0, h0, l1, h1;
        unpack2(accp[i][0], l0, h0); unpack2(accp[i][1], l1, h1);
        *(float4*)(out + base + pg * 4) =
            make_float4(l0 + xr0.x, h0 + xr0.y, l1 + xr0.z, h1 + xr0.w);
        unpack2(accp[i][2], l0, h0); unpack2(accp[i][3], l1, h1);
        *(float4*)(out + base + 64 + pg * 4) =
            make_float4(l0 + xr1.x, h0 + xr1.y, l1 + xr1.z, h1 + xr1.w);
    }
}

extern "C" void kernel_launch(void* const* d_in, const int* in_sizes, int n_in,
                              void* d_out, int out_size) {
    const float* x   = (const float*)d_in[0];
    const float* gnw = (const float*)d_in[1];
    const float* gnb = (const float*)d_in[2];
    const float* qw  = (const float*)d_in[3];
    const float* qb  = (const float*)d_in[4];
    const float* kw  = (const float*)d_in[5];
    const float* kb  = (const float*)d_in[6];
    const float* vw  = (const float*)d_in[7];
    const float* vb  = (const float*)d_in[8];
    const float* pw  = (const float*)d_in[9];
    float* out = (float*)d_out;

    k_pool_stats<<<dim3(784, BATCH), 256>>>(x);
    k_stats2<<<BATCH, 256>>>();
    k_qkvg<<<dim3(TG2, BATCH), 64>>>(gnw, gnb, qw, qb, kw, kb, vw, vb);
    k_qkv<<<dim3(HW / 128, BATCH), 128>>>(x, gnw, gnb, qw, qb, kw, kb, vw, vb);
    k_wm<<<dim3(GRIDK, BATCH), 416>>>();
    k_softmax_wm<<<dim3(P2, BATCH), 256>>>();
    k_wg<<<dim3(TG2 / 64, TG2 / 64, BATCH), 256>>>();
    k_softmax_wg<<<dim3(TG2, BATCH), 256>>>();
    k_hg<<<dim3(TG2 / 64, BATCH), 256>>>();
    k_hp<<<dim3(SPB / 128, BATCH), 256>>>();
    k_proj<<<dim3(HW / 128, BATCH), 128>>>(x, pw, out);
}

// round 10
// speedup vs baseline: 1.1649x; 1.1044x over previous
#include <cuda_runtime.h>

#define HW      200704          // 448*448
#define WID     448
#define CC      64
#define BATCH   2
#define TG2     3136            // 56*56
#define P2      196
#define P2P     200             // padded q-dim (pads stay zero: device globals are zero-init)
#define NPB     12845056        // C*HW per batch
#define SPB     65536           // S per batch
#define EPSV    1e-5f
#define GRIDK   74
#define KCHUNK  886             // ceil(65536/74)

typedef unsigned long long u64;
__device__ __forceinline__ u64 pack2(float lo, float hi) {
    u64 r; asm("mov.b64 %0,{%1,%2};" : "=l"(r) : "f"(lo), "f"(hi)); return r;
}
__device__ __forceinline__ void unpack2(u64 v, float& lo, float& hi) {
    asm("mov.b64 {%0,%1},%2;" : "=f"(lo), "=f"(hi) : "l"(v));
}
__device__ __forceinline__ u64 fma2(u64 a, u64 b, u64 c) {
    u64 d; asm("fma.rn.f32x2 %0,%1,%2,%3;" : "=l"(d) : "l"(a), "l"(b), "l"(c)); return d;
}

// ---- tf32 MMA helpers ----
__device__ __forceinline__ unsigned f2tf(float x) {
    unsigned r; asm("cvt.rna.tf32.f32 %0,%1;" : "=r"(r) : "f"(x)); return r;
}
__device__ __forceinline__ void split2(float x, unsigned& h, unsigned& l) {
    h = f2tf(x);
    l = f2tf(x - __uint_as_float(h));
}
__device__ __forceinline__ void mma_tf32(float* c, unsigned a0, unsigned a1, unsigned a2, unsigned a3,
                                         unsigned b0, unsigned b1) {
    asm volatile("mma.sync.aligned.m16n8k8.row.col.f32.tf32.tf32.f32 "
                 "{%0,%1,%2,%3},{%4,%5,%6,%7},{%8,%9},{%0,%1,%2,%3};"
                 : "+f"(c[0]), "+f"(c[1]), "+f"(c[2]), "+f"(c[3])
                 : "r"(a0), "r"(a1), "r"(a2), "r"(a3), "r"(b0), "r"(b1));
}

// ---------------- scratch ----------------
__device__ float g_q[BATCH * NPB];
__device__ float g_k[BATCH * NPB];
__device__ float g_v[BATCH * NPB];
__device__ float g_hin[BATCH * NPB];
__device__ float g_spart[BATCH * 784 * 2];
__device__ float g_stats[BATCH * 2];
__device__ float g_px[BATCH * CC * TG2];
__device__ float g_qg[BATCH * TG2 * CC];
__device__ float g_kg[BATCH * TG2 * CC];
__device__ float g_vg[BATCH * TG2 * CC];
__device__ float g_wmp[BATCH * GRIDK * P2 * P2];
__device__ float g_wmT[BATCH * P2 * P2P];
__device__ float g_hg[BATCH * TG2 * CC];

// ---------------- K1: 8x8 avg-pool of x + GN stat partials ----------------
__global__ __launch_bounds__(256) void k_pool_stats(const float* __restrict__ x) {
    int b = blockIdx.y;
    int idx = blockIdx.x * 256 + threadIdx.x;
    int c = idx / TG2;
    int cell = idx - c * TG2;
    int th = cell / 56, tw = cell - th * 56;
    const float* xp = x + ((size_t)b * CC + c) * HW + (size_t)(th * 8) * WID + tw * 8;
    float s = 0.f, s2 = 0.f;
#pragma unroll
    for (int r = 0; r < 8; r++) {
        float4 a = *(const float4*)(xp + r * WID);
        float4 bb = *(const float4*)(xp + r * WID + 4);
        s  += a.x + a.y + a.z + a.w + bb.x + bb.y + bb.z + bb.w;
        s2 += a.x*a.x + a.y*a.y + a.z*a.z + a.w*a.w
            + bb.x*bb.x + bb.y*bb.y + bb.z*bb.z + bb.w*bb.w;
    }
    g_px[(b * CC + c) * TG2 + cell] = s * (1.f / 64.f);

    __shared__ float r0[256], r1[256];
    int t = threadIdx.x;
    r0[t] = s; r1[t] = s2;
    __syncthreads();
    for (int o = 128; o > 0; o >>= 1) {
        if (t < o) { r0[t] += r0[t + o]; r1[t] += r1[t + o]; }
        __syncthreads();
    }
    if (t == 0) {
        g_spart[(b * 784 + blockIdx.x) * 2 + 0] = r0[0];
        g_spart[(b * 784 + blockIdx.x) * 2 + 1] = r1[0];
    }
}

// ---------------- K2: reduce stat partials ----------------
__global__ void k_stats2() {
    int b = blockIdx.x, t = threadIdx.x;
    float s = 0.f, s2 = 0.f;
    for (int i = t; i < 784; i += 256) {
        s  += g_spart[(b * 784 + i) * 2 + 0];
        s2 += g_spart[(b * 784 + i) * 2 + 1];
    }
    __shared__ float r0[256], r1[256];
    r0[t] = s; r1[t] = s2;
    __syncthreads();
    for (int o = 128; o > 0; o >>= 1) {
        if (t < o) { r0[t] += r0[t + o]; r1[t] += r1[t + o]; }
        __syncthreads();
    }
    if (t == 0) { g_stats[b * 2] = r0[0]; g_stats[b * 2 + 1] = r1[0]; }
}

// ---------------- K3: pooled qkv from pooled x ----------------
__global__ void k_qkvg(const float* __restrict__ gnw, const float* __restrict__ gnb,
                       const float* __restrict__ qw, const float* __restrict__ qb,
                       const float* __restrict__ kw, const float* __restrict__ kb,
                       const float* __restrict__ vw, const float* __restrict__ vb) {
    int b = blockIdx.y, cell = blockIdx.x, o = threadIdx.x;
    float mean = g_stats[b * 2] * (1.f / (float)NPB);
    float var  = g_stats[b * 2 + 1] * (1.f / (float)NPB) - mean * mean;
    float inv  = rsqrtf(var + EPSV);
    __shared__ float xn[64];
    xn[o] = (g_px[(b * CC + o) * TG2 + cell] - mean) * inv * gnw[o] + gnb[o];
    __syncthreads();
    float aq = qb[o], ak = kb[o], av = vb[o];
#pragma unroll 8
    for (int j = 0; j < 64; j++) {
        float xv = xn[j];
        aq += qw[o * 64 + j] * xv;
        ak += kw[o * 64 + j] * xv;
        av += vw[o * 64 + j] * xv;
    }
    int off = (b * TG2 + cell) * CC + o;
    g_qg[off] = aq; g_kg[off] = ak; g_vg[off] = av;
}

// ---------------- K4: GN + q/k/v convs, 8x8 tiles, FFMA2 ----------------
__global__ __launch_bounds__(128) void k_qkv(const float* __restrict__ x,
                                             const float* __restrict__ gnw, const float* __restrict__ gnb,
                                             const float* __restrict__ W0, const float* __restrict__ B0,
                                             const float* __restrict__ W1, const float* __restrict__ B1,
                                             const float* __restrict__ W2, const float* __restrict__ B2) {
    __shared__ __align__(16) float sXn[64][128];
    __shared__ __align__(16) float sWt[64][64];
    __shared__ float sB[64];
    int b = blockIdx.y;
    int pix0 = blockIdx.x * 128;
    int t = threadIdx.x;
    float mean = g_stats[b * 2] * (1.f / (float)NPB);
    float inv  = rsqrtf(g_stats[b * 2 + 1] * (1.f / (float)NPB) - mean * mean + EPSV);

    for (int i = t; i < 2048; i += 128) {
        int c = i >> 5, p4 = i & 31;
        float4 v = *(const float4*)(x + ((size_t)b * CC + c) * HW + pix0 + p4 * 4);
        float gw = gnw[c] * inv, gb = gnb[c] - mean * gnw[c] * inv;
        v.x = v.x * gw + gb; v.y = v.y * gw + gb;
        v.z = v.z * gw + gb; v.w = v.w * gw + gb;
        *(float4*)&sXn[c][p4 * 4] = v;
    }
    const float* Ws[3] = {W0, W1, W2};
    const float* Bs[3] = {B0, B1, B2};
    float* Os[3] = {g_q, g_k, g_v};
    int og = t >> 4, pg = t & 15;

    for (int m = 0; m < 3; m++) {
        __syncthreads();
        for (int i = t; i < 1024; i += 128) {
            int o = i & 63, c4 = i >> 6;
            float4 w = *(const float4*)(Ws[m] + o * 64 + c4 * 4);
            sWt[c4 * 4 + 0][o] = w.x;
            sWt[c4 * 4 + 1][o] = w.y;
            sWt[c4 * 4 + 2][o] = w.z;
            sWt[c4 * 4 + 3][o] = w.w;
        }
        if (t < 64) sB[t] = Bs[m][t];
        __syncthreads();

        u64 accp[8][4];
#pragma unroll
        for (int i = 0; i < 8; i++) {
            int o = og * 4 + ((i < 4) ? i : 28 + i);
            u64 bp = pack2(sB[o], sB[o]);
            accp[i][0] = bp; accp[i][1] = bp; accp[i][2] = bp; accp[i][3] = bp;
        }
#pragma unroll 8
        for (int c = 0; c < 64; c++) {
            const u64* xp = (const u64*)&sXn[c][pg * 4];
            const u64* xq = (const u64*)&sXn[c][pg * 4 + 64];
            u64 x0 = xp[0], x1 = xp[1], x2 = xq[0], x3 = xq[1];
            float4 w0 = *(const float4*)&sWt[c][og * 4];
            float4 w1 = *(const float4*)&sWt[c][og * 4 + 32];
            float aw[8] = {w0.x, w0.y, w0.z, w0.w, w1.x, w1.y, w1.z, w1.w};
#pragma unroll
            for (int i = 0; i < 8; i++) {
                u64 ad = pack2(aw[i], aw[i]);
                accp[i][0] = fma2(ad, x0, accp[i][0]);
                accp[i][1] = fma2(ad, x1, accp[i][1]);
                accp[i][2] = fma2(ad, x2, accp[i][2]);
                accp[i][3] = fma2(ad, x3, accp[i][3]);
            }
        }
        float* O = Os[m];
#pragma unroll
        for (int i = 0; i < 8; i++) {
            int o = og * 4 + ((i < 4) ? i : 28 + i);
            size_t base = ((size_t)b * CC + o) * HW + pix0;
            float l0, h0, l1, h1;
            unpack2(accp[i][0], l0, h0); unpack2(accp[i][1], l1, h1);
            *(float4*)(O + base + pg * 4) = make_float4(l0, h0, l1, h1);
            unpack2(accp[i][2], l0, h0); unpack2(accp[i][3], l1, h1);
            *(float4*)(O + base + 64 + pg * 4) = make_float4(l0, h0, l1, h1);
        }
    }
}

// ------- K5: wm split-K MMA, pre-split h/l smem, K-step 16, reg prefetch -------
#define WSTR 216
__global__ __launch_bounds__(416, 1) void k_wm() {
    int b = blockIdx.y, kb = blockIdx.x;
    int s0 = kb * KCHUNK, send = min(s0 + KCHUNK, SPB);
    const float* Q = g_q + (size_t)b * NPB;
    const float* K = g_k + (size_t)b * NPB;
    __shared__ __align__(16) unsigned Ah[16][WSTR], Al[16][WSTR];
    __shared__ __align__(16) unsigned Bh[16][WSTR], Bl[16][WSTR];
    int t = threadIdx.x;
    for (int i = t; i < 16 * WSTR; i += 416) {
        ((unsigned*)Ah)[i] = 0; ((unsigned*)Al)[i] = 0;
        ((unsigned*)Bh)[i] = 0; ((unsigned*)Bl)[i] = 0;
    }
    int lane = t & 31, w = t >> 5;
    int gid = lane >> 2, tig = lane & 3;
    int m0 = w * 16;
    float acc[25][4];
#pragma unroll
    for (int nt = 0; nt < 25; nt++) { acc[nt][0] = acc[nt][1] = acc[nt][2] = acc[nt][3] = 0.f; }

    bool ld = t < 392;
    int r0 = 0, c40 = 0, r1 = 0, c41 = 0;
    if (ld) { int i0 = 2 * t; r0 = i0 / 49; c40 = i0 - r0 * 49; r1 = (i0 + 1) / 49; c41 = (i0 + 1) - r1 * 49; }
    float4 pq0, pq1, pk0, pk1;
    float4 z4 = make_float4(0.f, 0.f, 0.f, 0.f);
    pq0 = pq1 = pk0 = pk1 = z4;
    if (ld) {
        int s = s0 + r0;
        if (s < send) { pq0 = *(const float4*)(Q + (size_t)s * 196 + c40 * 4);
                        pk0 = *(const float4*)(K + (size_t)s * 196 + c40 * 4); }
        s = s0 + r1;
        if (s < send) { pq1 = *(const float4*)(Q + (size_t)s * 196 + c41 * 4);
                        pk1 = *(const float4*)(K + (size_t)s * 196 + c41 * 4); }
    }

    for (int st = s0; st < send; st += 16) {
        __syncthreads();
        if (ld) {
            uint4 h, l;
            split2(pq0.x, h.x, l.x); split2(pq0.y, h.y, l.y);
            split2(pq0.z, h.z, l.z); split2(pq0.w, h.w, l.w);
            *(uint4*)&Ah[r0][c40 * 4] = h; *(uint4*)&Al[r0][c40 * 4] = l;
            split2(pk0.x, h.x, l.x); split2(pk0.y, h.y, l.y);
            split2(pk0.z, h.z, l.z); split2(pk0.w, h.w, l.w);
            *(uint4*)&Bh[r0][c40 * 4] = h; *(uint4*)&Bl[r0][c40 * 4] = l;
            split2(pq1.x, h.x, l.x); split2(pq1.y, h.y, l.y);
            split2(pq1.z, h.z, l.z); split2(pq1.w, h.w, l.w);
            *(uint4*)&Ah[r1][c41 * 4] = h; *(uint4*)&Al[r1][c41 * 4] = l;
            split2(pk1.x, h.x, l.x); split2(pk1.y, h.y, l.y);
            split2(pk1.z, h.z, l.z); split2(pk1.w, h.w, l.w);
            *(uint4*)&Bh[r1][c41 * 4] = h; *(uint4*)&Bl[r1][c41 * 4] = l;
        }
        __syncthreads();
        int stn = st + 16;
        if (ld && stn < send) {
            pq0 = pq1 = pk0 = pk1 = z4;
            int s = stn + r0;
            if (s < send) { pq0 = *(const float4*)(Q + (size_t)s * 196 + c40 * 4);
                            pk0 = *(const float4*)(K + (size_t)s * 196 + c40 * 4); }
            s = stn + r1;
            if (s < send) { pq1 = *(const float4*)(Q + (size_t)s * 196 + c41 * 4);
                            pk1 = *(const float4*)(K + (size_t)s * 196 + c41 * 4); }
        }
#pragma unroll
        for (int sub = 0; sub < 2; sub++) {
            int ra = sub * 8 + tig, rb = ra + 4;
            unsigned ah0 = Ah[ra][m0 + gid], ah1 = Ah[ra][m0 + gid + 8];
            unsigned ah2 = Ah[rb][m0 + gid], ah3 = Ah[rb][m0 + gid + 8];
            unsigned al0 = Al[ra][m0 + gid], al1 = Al[ra][m0 + gid + 8];
            unsigned al2 = Al[rb][m0 + gid], al3 = Al[rb][m0 + gid + 8];
#pragma unroll
            for (int nt = 0; nt < 25; nt++) {
                int n0 = nt * 8;
                unsigned bh0 = Bh[ra][n0 + gid], bh1 = Bh[rb][n0 + gid];
                unsigned bl0 = Bl[ra][n0 + gid], bl1 = Bl[rb][n0 + gid];
                mma_tf32(acc[nt], ah0, ah1, ah2, ah3, bh0, bh1);
                mma_tf32(acc[nt], ah0, ah1, ah2, ah3, bl0, bl1);
                mma_tf32(acc[nt], al0, al1, al2, al3, bh0, bh1);
            }
        }
    }
    float* out = g_wmp + ((size_t)b * GRIDK + kb) * (P2 * P2);
    int p0 = m0 + gid, p1 = p0 + 8;
#pragma unroll
    for (int nt = 0; nt < 25; nt++) {
        int q0 = nt * 8 + 2 * tig;
        if (p0 < 196) {
            if (q0 < 196)     out[p0 * 196 + q0]     = acc[nt][0];
            if (q0 + 1 < 196) out[p0 * 196 + q0 + 1] = acc[nt][1];
        }
        if (p1 < 196) {
            if (q0 < 196)     out[p1 * 196 + q0]     = acc[nt][2];
            if (q0 + 1 < 196) out[p1 * 196 + q0 + 1] = acc[nt][3];
        }
    }
}

// ---------------- K6: reduce wm partials + softmax + write padded wm^T ----------
__global__ void k_softmax_wm() {
    int b = blockIdx.y, p = blockIdx.x, t = threadIdx.x;
    __shared__ float red[256];
    float v = -3.0e38f;
    if (t < P2) {
        float s = 0.f;
        for (int r = 0; r < GRIDK; r++)
            s += g_wmp[((size_t)(b * GRIDK + r)) * (P2 * P2) + p * P2 + t];
        v = s * (1.f / 256.f);
    }
    red[t] = v;
    __syncthreads();
    for (int o = 128; o > 0; o >>= 1) {
        if (t < o) red[t] = fmaxf(red[t], red[t + o]);
        __syncthreads();
    }
    float mx = red[0];
    __syncthreads();
    float e = (t < P2) ? __expf(v - mx) : 0.f;
    red[t] = e;
    __syncthreads();
    for (int o = 128; o > 0; o >>= 1) {
        if (t < o) red[t] += red[t + o];
        __syncthreads();
    }
    float inv = 1.f / red[0];
    if (t < P2) g_wmT[(b * P2 + t) * P2P + p] = e * inv;
}

// ------- K7: fused global attention: softmax(qg.kgT/8).vg -> g_hg (flash) -------
__global__ __launch_bounds__(256) void k_gattn() {
    int b = blockIdx.y;
    int q0 = blockIdx.x * 32;
    __shared__ __align__(16) float Qsd[64][68];   // [ch][2*row] dup pairs
    __shared__ __align__(16) float Ktt[64][66];   // [ch][key]
    __shared__ __align__(16) float Vt[64][68];    // [key][ch]
    __shared__ __align__(16) float Psd[64][76];   // [key][2*row] dup pairs
    const float* Qg = g_qg + (size_t)b * TG2 * CC;
    const float* Kg = g_kg + (size_t)b * TG2 * CC;
    const float* Vg = g_vg + (size_t)b * TG2 * CC;
    int t = threadIdx.x;
    int tx = t & 31, ty = t >> 5;                 // warp = ty (8 warps x 4 rows)

    for (int i = t; i < 512; i += 256) {          // Q: 32 rows x 16 float4
        int r = i >> 4, c4 = i & 15;
        float4 q4 = *(const float4*)(Qg + (q0 + r) * 64 + c4 * 4);
        *(float2*)&Qsd[c4 * 4 + 0][2 * r] = make_float2(q4.x * 0.125f, q4.x * 0.125f);
        *(float2*)&Qsd[c4 * 4 + 1][2 * r] = make_float2(q4.y * 0.125f, q4.y * 0.125f);
        *(float2*)&Qsd[c4 * 4 + 2][2 * r] = make_float2(q4.z * 0.125f, q4.z * 0.125f);
        *(float2*)&Qsd[c4 * 4 + 3][2 * r] = make_float2(q4.w * 0.125f, q4.w * 0.125f);
    }
    u64 Oacc[4] = {0ull, 0ull, 0ull, 0ull};
    float m_[4] = {-3.0e38f, -3.0e38f, -3.0e38f, -3.0e38f};
    float l_[4] = {0.f, 0.f, 0.f, 0.f};

    for (int kc = 0; kc < 49; kc++) {
        int kb0 = kc * 64;
        __syncthreads();
        for (int i = t; i < 1024; i += 256) {     // K,V: 64 keys x 16 float4
            int key = i >> 4, c4 = i & 15;
            float4 k4 = *(const float4*)(Kg + (kb0 + key) * 64 + c4 * 4);
            Ktt[c4 * 4 + 0][key] = k4.x; Ktt[c4 * 4 + 1][key] = k4.y;
            Ktt[c4 * 4 + 2][key] = k4.z; Ktt[c4 * 4 + 3][key] = k4.w;
            *(float4*)&Vt[key][c4 * 4] = *(const float4*)(Vg + (kb0 + key) * 64 + c4 * 4);
        }
        __syncthreads();
        u64 s[4] = {0ull, 0ull, 0ull, 0ull};
#pragma unroll 16
        for (int ch = 0; ch < 64; ch++) {
            const u64* ap = (const u64*)&Qsd[ch][8 * ty];
            u64 bv = *(const u64*)&Ktt[ch][2 * tx];
            s[0] = fma2(ap[0], bv, s[0]);
            s[1] = fma2(ap[1], bv, s[1]);
            s[2] = fma2(ap[2], bv, s[2]);
            s[3] = fma2(ap[3], bv, s[3]);
        }
#pragma unroll
        for (int j = 0; j < 4; j++) {
            float sa, sb; unpack2(s[j], sa, sb);
            float mx = fmaxf(sa, sb);
#pragma unroll
            for (int off = 16; off > 0; off >>= 1)
                mx = fmaxf(mx, __shfl_xor_sync(0xffffffffu, mx, off));
            float mn = fmaxf(m_[j], mx);
            float al = __expf(m_[j] - mn);
            float p0 = __expf(sa - mn), p1 = __expf(sb - mn);
            float rs = p0 + p1;
#pragma unroll
            for (int off = 16; off > 0; off >>= 1)
                rs += __shfl_xor_sync(0xffffffffu, rs, off);
            l_[j] = l_[j] * al + rs;
            m_[j] = mn;
            Oacc[j] = fma2(pack2(al, al), Oacc[j], 0ull);
            *(float2*)&Psd[2 * tx][8 * ty + 2 * j]     = make_float2(p0, p0);
            *(float2*)&Psd[2 * tx + 1][8 * ty + 2 * j] = make_float2(p1, p1);
        }
        __syncthreads();
#pragma unroll 16
        for (int key = 0; key < 64; key++) {
            const u64* pp = (const u64*)&Psd[key][8 * ty];
            u64 vv = *(const u64*)&Vt[key][2 * tx];
            Oacc[0] = fma2(pp[0], vv, Oacc[0]);
            Oacc[1] = fma2(pp[1], vv, Oacc[1]);
            Oacc[2] = fma2(pp[2], vv, Oacc[2]);
            Oacc[3] = fma2(pp[3], vv, Oacc[3]);
        }
    }
#pragma unroll
    for (int j = 0; j < 4; j++) {
        float inv = 1.f / l_[j];
        float o0, o1; unpack2(Oacc[j], o0, o1);
        size_t base = ((size_t)(b * TG2) + q0 + 4 * ty + j) * 64 + 2 * tx;
        g_hg[base]     = o0 * inv;
        g_hg[base + 1] = o1 * inv;
    }
}

// ------- K8: hp = V*wm^T MMA, pre-split h/l smem, K-step 16 -------
#define HAS 136
#define HBS 216
__global__ __launch_bounds__(256, 2) void k_hp() {
    int b = blockIdx.y;
    int s0 = blockIdx.x * 128;
    const float* V = g_v + (size_t)b * NPB;
    const float* W = g_wmT + (size_t)b * (P2 * P2P);
    __shared__ __align__(16) unsigned Avh[16][HAS], Avl[16][HAS];
    __shared__ __align__(16) unsigned Bwh[16][HBS], Bwl[16][HBS];
    int t = threadIdx.x;
    for (int i = t; i < 16 * HAS; i += 256) { ((unsigned*)Avh)[i] = 0; ((unsigned*)Avl)[i] = 0; }
    for (int i = t; i < 16 * HBS; i += 256) { ((unsigned*)Bwh)[i] = 0; ((unsigned*)Bwl)[i] = 0; }
    int lane = t & 31, w = t >> 5;
    int gid = lane >> 2, tig = lane & 3;
    int m0 = w * 16;
    float acc[25][4];
#pragma unroll
    for (int nt = 0; nt < 25; nt++) { acc[nt][0] = acc[nt][1] = acc[nt][2] = acc[nt][3] = 0.f; }

    for (int k0 = 0; k0 < 208; k0 += 16) {
        __syncthreads();
        for (int ii = 0; ii < 2; ii++) {           // V tile: 128 rows x 4 float4
            int i = 2 * t + ii;
            int r = i >> 2, kq = i & 3;
            int kbase = k0 + kq * 4;
            float4 vv = make_float4(0.f, 0.f, 0.f, 0.f);
            if (kbase < 196) vv = *(const float4*)(V + (size_t)(s0 + r) * 196 + kbase);
            unsigned h, l;
            split2(vv.x, h, l); Avh[kq * 4 + 0][r] = h; Avl[kq * 4 + 0][r] = l;
            split2(vv.y, h, l); Avh[kq * 4 + 1][r] = h; Avl[kq * 4 + 1][r] = l;
            split2(vv.z, h, l); Avh[kq * 4 + 2][r] = h; Avl[kq * 4 + 2][r] = l;
            split2(vv.w, h, l); Avh[kq * 4 + 3][r] = h; Avl[kq * 4 + 3][r] = l;
        }
        for (int i = t; i < 800; i += 256) {       // W tile: 16 rows x 50 float4
            int r = i / 50, c4 = i - (i / 50) * 50;
            int kg = k0 + r;
            float4 wv = make_float4(0.f, 0.f, 0.f, 0.f);
            if (kg < 196) wv = *(const float4*)(W + (size_t)kg * P2P + c4 * 4);
            uint4 h, l;
            split2(wv.x, h.x, l.x); split2(wv.y, h.y, l.y);
            split2(wv.z, h.z, l.z); split2(wv.w, h.w, l.w);
            *(uint4*)&Bwh[r][c4 * 4] = h; *(uint4*)&Bwl[r][c4 * 4] = l;
        }
        __syncthreads();
#pragma unroll
        for (int sub = 0; sub < 2; sub++) {
            int ra = sub * 8 + tig, rb = ra + 4;
            unsigned ah0 = Avh[ra][m0 + gid], ah1 = Avh[ra][m0 + gid + 8];
            unsigned ah2 = Avh[rb][m0 + gid], ah3 = Avh[rb][m0 + gid + 8];
            unsigned al0 = Avl[ra][m0 + gid], al1 = Avl[ra][m0 + gid + 8];
            unsigned al2 = Avl[rb][m0 + gid], al3 = Avl[rb][m0 + gid + 8];
#pragma unroll
            for (int nt = 0; nt < 25; nt++) {
                int n0 = nt * 8;
                unsigned bh0 = Bwh[ra][n0 + gid], bh1 = Bwh[rb][n0 + gid];
                unsigned bl0 = Bwl[ra][n0 + gid], bl1 = Bwl[rb][n0 + gid];
                mma_tf32(acc[nt], ah0, ah1, ah2, ah3, bh0, bh1);
                mma_tf32(acc[nt], ah0, ah1, ah2, ah3, bl0, bl1);
                mma_tf32(acc[nt], al0, al1, al2, al3, bh0, bh1);
            }
        }
    }
    float* O = g_hin + (size_t)b * NPB;
    size_t r0 = (size_t)(s0 + m0 + gid) * 196;
    size_t r1 = r0 + 8 * 196;
#pragma unroll
    for (int nt = 0; nt < 25; nt++) {
        int q0 = nt * 8 + 2 * tig;
        if (q0 < 196) {
            O[r0 + q0] = acc[nt][0];
            O[r1 + q0] = acc[nt][2];
            if (q0 + 1 < 196) {
                O[r0 + q0 + 1] = acc[nt][1];
                O[r1 + q0 + 1] = acc[nt][3];
            }
        }
    }
}

// ---------------- K9: proj fused blend + conv + residual, FFMA2 ----------------
__global__ __launch_bounds__(128) void k_proj(const float* __restrict__ x,
                                              const float* __restrict__ pw,
                                              float* __restrict__ out) {
    __shared__ __align__(16) float sH[64][128];
    __shared__ __align__(16) float sWt[64][64];
    int b = blockIdx.y;
    int pix0 = blockIdx.x * 128;
    int t = threadIdx.x;

    for (int i = t; i < 2048; i += 128) {
        int c = i >> 5, p4 = i & 31;
        int pgl = pix0 + p4 * 4;
        int h = pgl / WID, w = pgl - h * WID;
        int cell = (h >> 3) * 56 + (w >> 3);
        float4 hp = *(const float4*)(g_hin + (size_t)b * NPB + (size_t)c * HW + pgl);
        float hg = g_hg[(size_t)(b * TG2 + cell) * 64 + c] * 0.25f;
        float4 r = make_float4(0.75f * hp.x + hg, 0.75f * hp.y + hg,
                               0.75f * hp.z + hg, 0.75f * hp.w + hg);
        *(float4*)&sH[c][p4 * 4] = r;
    }
    for (int i = t; i < 1024; i += 128) {
        int o = i & 63, c4 = i >> 6;
        float4 w = *(const float4*)(pw + o * 64 + c4 * 4);
        sWt[c4 * 4 + 0][o] = w.x;
        sWt[c4 * 4 + 1][o] = w.y;
        sWt[c4 * 4 + 2][o] = w.z;
        sWt[c4 * 4 + 3][o] = w.w;
    }
    __syncthreads();

    int og = t >> 4, pg = t & 15;
    u64 accp[8][4];
#pragma unroll
    for (int i = 0; i < 8; i++)
#pragma unroll
        for (int j = 0; j < 4; j++) accp[i][j] = 0ull;

#pragma unroll 8
    for (int c = 0; c < 64; c++) {
        const u64* xp = (const u64*)&sH[c][pg * 4];
        const u64* xq = (const u64*)&sH[c][pg * 4 + 64];
        u64 x0 = xp[0], x1 = xp[1], x2 = xq[0], x3 = xq[1];
        float4 w0 = *(const float4*)&sWt[c][og * 4];
        float4 w1 = *(const float4*)&sWt[c][og * 4 + 32];
        float aw[8] = {w0.x, w0.y, w0.z, w0.w, w1.x, w1.y, w1.z, w1.w};
#pragma unroll
        for (int i = 0; i < 8; i++) {
            u64 ad = pack2(aw[i], aw[i]);
            accp[i][0] = fma2(ad, x0, accp[i][0]);
            accp[i][1] = fma2(ad, x1, accp[i][1]);
            accp[i][2] = fma2(ad, x2, accp[i][2]);
            accp[i][3] = fma2(ad, x3, accp[i][3]);
        }
    }
#pragma unroll
    for (int i = 0; i < 8; i++) {
        int o = og * 4 + ((i < 4) ? i : 28 + i);
        size_t base = ((size_t)b * CC + o) * HW + pix0;
        float4 xr0 = *(const float4*)(x + base + pg * 4);
        float4 xr1 = *(const float4*)(x + base + 64 + pg * 4);
        float l0, h0, l1, h1;
        unpack2(accp[i][0], l0, h0); unpack2(accp[i][1], l1, h1);
        *(float4*)(out + base + pg * 4) =
            make_float4(l0 + xr0.x, h0 + xr0.y, l1 + xr0.z, h1 + xr0.w);
        unpack2(accp[i][2], l0, h0); unpack2(accp[i][3], l1, h1);
        *(float4*)(out + base + 64 + pg * 4) =
            make_float4(l0 + xr1.x, h0 + xr1.y, l1 + xr1.z, h1 + xr1.w);
    }
}

extern "C" void kernel_launch(void* const* d_in, const int* in_sizes, int n_in,
                              void* d_out, int out_size) {
    const float* x   = (const float*)d_in[0];
    const float* gnw = (const float*)d_in[1];
    const float* gnb = (const float*)d_in[2];
    const float* qw  = (const float*)d_in[3];
    const float* qb  = (const float*)d_in[4];
    const float* kw  = (const float*)d_in[5];
    const float* kb  = (const float*)d_in[6];
    const float* vw  = (const float*)d_in[7];
    const float* vb  = (const float*)d_in[8];
    const float* pw  = (const float*)d_in[9];
    float* out = (float*)d_out;

    k_pool_stats<<<dim3(784, BATCH), 256>>>(x);
    k_stats2<<<BATCH, 256>>>();
    k_qkvg<<<dim3(TG2, BATCH), 64>>>(gnw, gnb, qw, qb, kw, kb, vw, vb);
    k_qkv<<<dim3(HW / 128, BATCH), 128>>>(x, gnw, gnb, qw, qb, kw, kb, vw, vb);
    k_wm<<<dim3(GRIDK, BATCH), 416>>>();
    k_softmax_wm<<<dim3(P2, BATCH), 256>>>();
    k_gattn<<<dim3(TG2 / 32, BATCH), 256>>>();
    k_hp<<<dim3(SPB / 128, BATCH), 256>>>();
    k_proj<<<dim3(HW / 128, BATCH), 128>>>(x, pw, out);
}

// round 11
// speedup vs baseline: 1.1692x; 1.0037x over previous
#include <cuda_runtime.h>

#define HW      200704          // 448*448
#define WID     448
#define CC      64
#define BATCH   2
#define TG2     3136            // 56*56
#define P2      196
#define P2P     200             // padded q-dim (pads stay zero: device globals are zero-init)
#define NPB     12845056        // C*HW per batch
#define SPB     65536           // S per batch
#define EPSV    1e-5f
#define GRIDK   74
#define KCHUNK  886             // ceil(65536/74)

typedef unsigned long long u64;
__device__ __forceinline__ u64 pack2(float lo, float hi) {
    u64 r; asm("mov.b64 %0,{%1,%2};" : "=l"(r) : "f"(lo), "f"(hi)); return r;
}
__device__ __forceinline__ void unpack2(u64 v, float& lo, float& hi) {
    asm("mov.b64 {%0,%1},%2;" : "=f"(lo), "=f"(hi) : "l"(v));
}
__device__ __forceinline__ u64 fma2(u64 a, u64 b, u64 c) {
    u64 d; asm("fma.rn.f32x2 %0,%1,%2,%3;" : "=l"(d) : "l"(a), "l"(b), "l"(c)); return d;
}

// ---- tf32 MMA helpers ----
__device__ __forceinline__ unsigned f2tf(float x) {
    unsigned r; asm("cvt.rna.tf32.f32 %0,%1;" : "=r"(r) : "f"(x)); return r;
}
__device__ __forceinline__ void split2(float x, unsigned& h, unsigned& l) {
    h = f2tf(x);
    l = f2tf(x - __uint_as_float(h));
}
__device__ __forceinline__ void mma_tf32(float* c, unsigned a0, unsigned a1, unsigned a2, unsigned a3,
                                         unsigned b0, unsigned b1) {
    asm volatile("mma.sync.aligned.m16n8k8.row.col.f32.tf32.tf32.f32 "
                 "{%0,%1,%2,%3},{%4,%5,%6,%7},{%8,%9},{%0,%1,%2,%3};"
                 : "+f"(c[0]), "+f"(c[1]), "+f"(c[2]), "+f"(c[3])
                 : "r"(a0), "r"(a1), "r"(a2), "r"(a3), "r"(b0), "r"(b1));
}

// ---------------- scratch ----------------
__device__ float g_q[BATCH * NPB];
__device__ float g_k[BATCH * NPB];
__device__ float g_v[BATCH * NPB];
__device__ float g_hin[BATCH * NPB];
__device__ float g_spart[BATCH * 784 * 2];
__device__ float g_stats[BATCH * 2];
__device__ float g_px[BATCH * CC * TG2];
__device__ float g_qg[BATCH * TG2 * CC];
__device__ float g_kg[BATCH * TG2 * CC];
__device__ float g_vg[BATCH * TG2 * CC];
__device__ float g_wmp[BATCH * GRIDK * P2 * P2];
__device__ float g_wmT[BATCH * P2 * P2P];
__device__ float g_hg[BATCH * TG2 * CC];

// ---------------- K1: 8x8 avg-pool of x + GN stat partials ----------------
__global__ __launch_bounds__(256) void k_pool_stats(const float* __restrict__ x) {
    int b = blockIdx.y;
    int idx = blockIdx.x * 256 + threadIdx.x;
    int c = idx / TG2;
    int cell = idx - c * TG2;
    int th = cell / 56, tw = cell - th * 56;
    const float* xp = x + ((size_t)b * CC + c) * HW + (size_t)(th * 8) * WID + tw * 8;
    float s = 0.f, s2 = 0.f;
#pragma unroll
    for (int r = 0; r < 8; r++) {
        float4 a = *(const float4*)(xp + r * WID);
        float4 bb = *(const float4*)(xp + r * WID + 4);
        s  += a.x + a.y + a.z + a.w + bb.x + bb.y + bb.z + bb.w;
        s2 += a.x*a.x + a.y*a.y + a.z*a.z + a.w*a.w
            + bb.x*bb.x + bb.y*bb.y + bb.z*bb.z + bb.w*bb.w;
    }
    g_px[(b * CC + c) * TG2 + cell] = s * (1.f / 64.f);

    __shared__ float r0[256], r1[256];
    int t = threadIdx.x;
    r0[t] = s; r1[t] = s2;
    __syncthreads();
    for (int o = 128; o > 0; o >>= 1) {
        if (t < o) { r0[t] += r0[t + o]; r1[t] += r1[t + o]; }
        __syncthreads();
    }
    if (t == 0) {
        g_spart[(b * 784 + blockIdx.x) * 2 + 0] = r0[0];
        g_spart[(b * 784 + blockIdx.x) * 2 + 1] = r1[0];
    }
}

// ---------------- K2: reduce stat partials ----------------
__global__ void k_stats2() {
    int b = blockIdx.x, t = threadIdx.x;
    float s = 0.f, s2 = 0.f;
    for (int i = t; i < 784; i += 256) {
        s  += g_spart[(b * 784 + i) * 2 + 0];
        s2 += g_spart[(b * 784 + i) * 2 + 1];
    }
    __shared__ float r0[256], r1[256];
    r0[t] = s; r1[t] = s2;
    __syncthreads();
    for (int o = 128; o > 0; o >>= 1) {
        if (t < o) { r0[t] += r0[t + o]; r1[t] += r1[t + o]; }
        __syncthreads();
    }
    if (t == 0) { g_stats[b * 2] = r0[0]; g_stats[b * 2 + 1] = r1[0]; }
}

// ---------------- K3: pooled qkv from pooled x ----------------
__global__ void k_qkvg(const float* __restrict__ gnw, const float* __restrict__ gnb,
                       const float* __restrict__ qw, const float* __restrict__ qb,
                       const float* __restrict__ kw, const float* __restrict__ kb,
                       const float* __restrict__ vw, const float* __restrict__ vb) {
    int b = blockIdx.y, cell = blockIdx.x, o = threadIdx.x;
    float mean = g_stats[b * 2] * (1.f / (float)NPB);
    float var  = g_stats[b * 2 + 1] * (1.f / (float)NPB) - mean * mean;
    float inv  = rsqrtf(var + EPSV);
    __shared__ float xn[64];
    xn[o] = (g_px[(b * CC + o) * TG2 + cell] - mean) * inv * gnw[o] + gnb[o];
    __syncthreads();
    float aq = qb[o], ak = kb[o], av = vb[o];
#pragma unroll 8
    for (int j = 0; j < 64; j++) {
        float xv = xn[j];
        aq += qw[o * 64 + j] * xv;
        ak += kw[o * 64 + j] * xv;
        av += vw[o * 64 + j] * xv;
    }
    int off = (b * TG2 + cell) * CC + o;
    g_qg[off] = aq; g_kg[off] = ak; g_vg[off] = av;
}

// ---------------- K4: GN + q/k/v convs, 8x8 tiles, FFMA2 ----------------
__global__ __launch_bounds__(128) void k_qkv(const float* __restrict__ x,
                                             const float* __restrict__ gnw, const float* __restrict__ gnb,
                                             const float* __restrict__ W0, const float* __restrict__ B0,
                                             const float* __restrict__ W1, const float* __restrict__ B1,
                                             const float* __restrict__ W2, const float* __restrict__ B2) {
    __shared__ __align__(16) float sXn[64][128];
    __shared__ __align__(16) float sWt[64][64];
    __shared__ float sB[64];
    int b = blockIdx.y;
    int pix0 = blockIdx.x * 128;
    int t = threadIdx.x;
    float mean = g_stats[b * 2] * (1.f / (float)NPB);
    float inv  = rsqrtf(g_stats[b * 2 + 1] * (1.f / (float)NPB) - mean * mean + EPSV);

    for (int i = t; i < 2048; i += 128) {
        int c = i >> 5, p4 = i & 31;
        float4 v = *(const float4*)(x + ((size_t)b * CC + c) * HW + pix0 + p4 * 4);
        float gw = gnw[c] * inv, gb = gnb[c] - mean * gnw[c] * inv;
        v.x = v.x * gw + gb; v.y = v.y * gw + gb;
        v.z = v.z * gw + gb; v.w = v.w * gw + gb;
        *(float4*)&sXn[c][p4 * 4] = v;
    }
    const float* Ws[3] = {W0, W1, W2};
    const float* Bs[3] = {B0, B1, B2};
    float* Os[3] = {g_q, g_k, g_v};
    int og = t >> 4, pg = t & 15;

    for (int m = 0; m < 3; m++) {
        __syncthreads();
        for (int i = t; i < 1024; i += 128) {
            int o = i & 63, c4 = i >> 6;
            float4 w = *(const float4*)(Ws[m] + o * 64 + c4 * 4);
            sWt[c4 * 4 + 0][o] = w.x;
            sWt[c4 * 4 + 1][o] = w.y;
            sWt[c4 * 4 + 2][o] = w.z;
            sWt[c4 * 4 + 3][o] = w.w;
        }
        if (t < 64) sB[t] = Bs[m][t];
        __syncthreads();

        u64 accp[8][4];
#pragma unroll
        for (int i = 0; i < 8; i++) {
            int o = og * 4 + ((i < 4) ? i : 28 + i);
            u64 bp = pack2(sB[o], sB[o]);
            accp[i][0] = bp; accp[i][1] = bp; accp[i][2] = bp; accp[i][3] = bp;
        }
#pragma unroll 8
        for (int c = 0; c < 64; c++) {
            const u64* xp = (const u64*)&sXn[c][pg * 4];
            const u64* xq = (const u64*)&sXn[c][pg * 4 + 64];
            u64 x0 = xp[0], x1 = xp[1], x2 = xq[0], x3 = xq[1];
            float4 w0 = *(const float4*)&sWt[c][og * 4];
            float4 w1 = *(const float4*)&sWt[c][og * 4 + 32];
            float aw[8] = {w0.x, w0.y, w0.z, w0.w, w1.x, w1.y, w1.z, w1.w};
#pragma unroll
            for (int i = 0; i < 8; i++) {
                u64 ad = pack2(aw[i], aw[i]);
                accp[i][0] = fma2(ad, x0, accp[i][0]);
                accp[i][1] = fma2(ad, x1, accp[i][1]);
                accp[i][2] = fma2(ad, x2, accp[i][2]);
                accp[i][3] = fma2(ad, x3, accp[i][3]);
            }
        }
        float* O = Os[m];
#pragma unroll
        for (int i = 0; i < 8; i++) {
            int o = og * 4 + ((i < 4) ? i : 28 + i);
            size_t base = ((size_t)b * CC + o) * HW + pix0;
            float l0, h0, l1, h1;
            unpack2(accp[i][0], l0, h0); unpack2(accp[i][1], l1, h1);
            *(float4*)(O + base + pg * 4) = make_float4(l0, h0, l1, h1);
            unpack2(accp[i][2], l0, h0); unpack2(accp[i][3], l1, h1);
            *(float4*)(O + base + 64 + pg * 4) = make_float4(l0, h0, l1, h1);
        }
    }
}

// ------- K5: wm split-K MMA, pre-split h/l smem, K-step 16, reg prefetch -------
#define WSTR 216
__global__ __launch_bounds__(416, 1) void k_wm() {
    int b = blockIdx.y, kb = blockIdx.x;
    int s0 = kb * KCHUNK, send = min(s0 + KCHUNK, SPB);
    const float* Q = g_q + (size_t)b * NPB;
    const float* K = g_k + (size_t)b * NPB;
    __shared__ __align__(16) unsigned Ah[16][WSTR], Al[16][WSTR];
    __shared__ __align__(16) unsigned Bh[16][WSTR], Bl[16][WSTR];
    int t = threadIdx.x;
    for (int i = t; i < 16 * WSTR; i += 416) {
        ((unsigned*)Ah)[i] = 0; ((unsigned*)Al)[i] = 0;
        ((unsigned*)Bh)[i] = 0; ((unsigned*)Bl)[i] = 0;
    }
    int lane = t & 31, w = t >> 5;
    int gid = lane >> 2, tig = lane & 3;
    int m0 = w * 16;
    float acc[25][4];
#pragma unroll
    for (int nt = 0; nt < 25; nt++) { acc[nt][0] = acc[nt][1] = acc[nt][2] = acc[nt][3] = 0.f; }

    bool ld = t < 392;
    int r0 = 0, c40 = 0, r1 = 0, c41 = 0;
    if (ld) { int i0 = 2 * t; r0 = i0 / 49; c40 = i0 - r0 * 49; r1 = (i0 + 1) / 49; c41 = (i0 + 1) - r1 * 49; }
    float4 pq0, pq1, pk0, pk1;
    float4 z4 = make_float4(0.f, 0.f, 0.f, 0.f);
    pq0 = pq1 = pk0 = pk1 = z4;
    if (ld) {
        int s = s0 + r0;
        if (s < send) { pq0 = *(const float4*)(Q + (size_t)s * 196 + c40 * 4);
                        pk0 = *(const float4*)(K + (size_t)s * 196 + c40 * 4); }
        s = s0 + r1;
        if (s < send) { pq1 = *(const float4*)(Q + (size_t)s * 196 + c41 * 4);
                        pk1 = *(const float4*)(K + (size_t)s * 196 + c41 * 4); }
    }

    for (int st = s0; st < send; st += 16) {
        __syncthreads();
        if (ld) {
            uint4 h, l;
            split2(pq0.x, h.x, l.x); split2(pq0.y, h.y, l.y);
            split2(pq0.z, h.z, l.z); split2(pq0.w, h.w, l.w);
            *(uint4*)&Ah[r0][c40 * 4] = h; *(uint4*)&Al[r0][c40 * 4] = l;
            split2(pk0.x, h.x, l.x); split2(pk0.y, h.y, l.y);
            split2(pk0.z, h.z, l.z); split2(pk0.w, h.w, l.w);
            *(uint4*)&Bh[r0][c40 * 4] = h; *(uint4*)&Bl[r0][c40 * 4] = l;
            split2(pq1.x, h.x, l.x); split2(pq1.y, h.y, l.y);
            split2(pq1.z, h.z, l.z); split2(pq1.w, h.w, l.w);
            *(uint4*)&Ah[r1][c41 * 4] = h; *(uint4*)&Al[r1][c41 * 4] = l;
            split2(pk1.x, h.x, l.x); split2(pk1.y, h.y, l.y);
            split2(pk1.z, h.z, l.z); split2(pk1.w, h.w, l.w);
            *(uint4*)&Bh[r1][c41 * 4] = h; *(uint4*)&Bl[r1][c41 * 4] = l;
        }
        __syncthreads();
        int stn = st + 16;
        if (ld && stn < send) {
            pq0 = pq1 = pk0 = pk1 = z4;
            int s = stn + r0;
            if (s < send) { pq0 = *(const float4*)(Q + (size_t)s * 196 + c40 * 4);
                            pk0 = *(const float4*)(K + (size_t)s * 196 + c40 * 4); }
            s = stn + r1;
            if (s < send) { pq1 = *(const float4*)(Q + (size_t)s * 196 + c41 * 4);
                            pk1 = *(const float4*)(K + (size_t)s * 196 + c41 * 4); }
        }
#pragma unroll
        for (int sub = 0; sub < 2; sub++) {
            int ra = sub * 8 + tig, rb = ra + 4;
            unsigned ah0 = Ah[ra][m0 + gid], ah1 = Ah[ra][m0 + gid + 8];
            unsigned ah2 = Ah[rb][m0 + gid], ah3 = Ah[rb][m0 + gid + 8];
            unsigned al0 = Al[ra][m0 + gid], al1 = Al[ra][m0 + gid + 8];
            unsigned al2 = Al[rb][m0 + gid], al3 = Al[rb][m0 + gid + 8];
#pragma unroll
            for (int nt = 0; nt < 25; nt++) {
                int n0 = nt * 8;
                unsigned bh0 = Bh[ra][n0 + gid], bh1 = Bh[rb][n0 + gid];
                unsigned bl0 = Bl[ra][n0 + gid], bl1 = Bl[rb][n0 + gid];
                mma_tf32(acc[nt], ah0, ah1, ah2, ah3, bh0, bh1);
                mma_tf32(acc[nt], ah0, ah1, ah2, ah3, bl0, bl1);
                mma_tf32(acc[nt], al0, al1, al2, al3, bh0, bh1);
            }
        }
    }
    float* out = g_wmp + ((size_t)b * GRIDK + kb) * (P2 * P2);
    int p0 = m0 + gid, p1 = p0 + 8;
#pragma unroll
    for (int nt = 0; nt < 25; nt++) {
        int q0 = nt * 8 + 2 * tig;
        if (p0 < 196) {
            if (q0 < 196)     out[p0 * 196 + q0]     = acc[nt][0];
            if (q0 + 1 < 196) out[p0 * 196 + q0 + 1] = acc[nt][1];
        }
        if (p1 < 196) {
            if (q0 < 196)     out[p1 * 196 + q0]     = acc[nt][2];
            if (q0 + 1 < 196) out[p1 * 196 + q0 + 1] = acc[nt][3];
        }
    }
}

// ---------------- K6: reduce wm partials + softmax + write padded wm^T ----------
__global__ void k_softmax_wm() {
    int b = blockIdx.y, p = blockIdx.x, t = threadIdx.x;
    __shared__ float red[256];
    float v = -3.0e38f;
    if (t < P2) {
        float s = 0.f;
        for (int r = 0; r < GRIDK; r++)
            s += g_wmp[((size_t)(b * GRIDK + r)) * (P2 * P2) + p * P2 + t];
        v = s * (1.f / 256.f);
    }
    red[t] = v;
    __syncthreads();
    for (int o = 128; o > 0; o >>= 1) {
        if (t < o) red[t] = fmaxf(red[t], red[t + o]);
        __syncthreads();
    }
    float mx = red[0];
    __syncthreads();
    float e = (t < P2) ? __expf(v - mx) : 0.f;
    red[t] = e;
    __syncthreads();
    for (int o = 128; o > 0; o >>= 1) {
        if (t < o) red[t] += red[t + o];
        __syncthreads();
    }
    float inv = 1.f / red[0];
    if (t < P2) g_wmT[(b * P2 + t) * P2P + p] = e * inv;
}

// ------- K7: fused global attention: softmax(qg.kgT/8).vg -> g_hg (flash) -------
__global__ __launch_bounds__(256) void k_gattn() {
    int b = blockIdx.y;
    int q0 = blockIdx.x * 32;
    __shared__ __align__(16) float Qsd[64][68];   // [ch][2*row] dup pairs
    __shared__ __align__(16) float Ktt[64][66];   // [ch][key]
    __shared__ __align__(16) float Vt[64][68];    // [key][ch]
    __shared__ __align__(16) float Psd[64][76];   // [key][2*row] dup pairs
    const float* Qg = g_qg + (size_t)b * TG2 * CC;
    const float* Kg = g_kg + (size_t)b * TG2 * CC;
    const float* Vg = g_vg + (size_t)b * TG2 * CC;
    int t = threadIdx.x;
    int tx = t & 31, ty = t >> 5;                 // warp = ty (8 warps x 4 rows)

    for (int i = t; i < 512; i += 256) {          // Q: 32 rows x 16 float4
        int r = i >> 4, c4 = i & 15;
        float4 q4 = *(const float4*)(Qg + (q0 + r) * 64 + c4 * 4);
        *(float2*)&Qsd[c4 * 4 + 0][2 * r] = make_float2(q4.x * 0.125f, q4.x * 0.125f);
        *(float2*)&Qsd[c4 * 4 + 1][2 * r] = make_float2(q4.y * 0.125f, q4.y * 0.125f);
        *(float2*)&Qsd[c4 * 4 + 2][2 * r] = make_float2(q4.z * 0.125f, q4.z * 0.125f);
        *(float2*)&Qsd[c4 * 4 + 3][2 * r] = make_float2(q4.w * 0.125f, q4.w * 0.125f);
    }
    u64 Oacc[4] = {0ull, 0ull, 0ull, 0ull};
    float m_[4] = {-3.0e38f, -3.0e38f, -3.0e38f, -3.0e38f};
    float l_[4] = {0.f, 0.f, 0.f, 0.f};

    for (int kc = 0; kc < 49; kc++) {
        int kb0 = kc * 64;
        __syncthreads();
        for (int i = t; i < 1024; i += 256) {     // K,V: 64 keys x 16 float4
            int key = i >> 4, c4 = i & 15;
            float4 k4 = *(const float4*)(Kg + (kb0 + key) * 64 + c4 * 4);
            Ktt[c4 * 4 + 0][key] = k4.x; Ktt[c4 * 4 + 1][key] = k4.y;
            Ktt[c4 * 4 + 2][key] = k4.z; Ktt[c4 * 4 + 3][key] = k4.w;
            *(float4*)&Vt[key][c4 * 4] = *(const float4*)(Vg + (kb0 + key) * 64 + c4 * 4);
        }
        __syncthreads();
        u64 s[4] = {0ull, 0ull, 0ull, 0ull};
#pragma unroll 16
        for (int ch = 0; ch < 64; ch++) {
            const u64* ap = (const u64*)&Qsd[ch][8 * ty];
            u64 bv = *(const u64*)&Ktt[ch][2 * tx];
            s[0] = fma2(ap[0], bv, s[0]);
            s[1] = fma2(ap[1], bv, s[1]);
            s[2] = fma2(ap[2], bv, s[2]);
            s[3] = fma2(ap[3], bv, s[3]);
        }
#pragma unroll
        for (int j = 0; j < 4; j++) {
            float sa, sb; unpack2(s[j], sa, sb);
            float mx = fmaxf(sa, sb);
#pragma unroll
            for (int off = 16; off > 0; off >>= 1)
                mx = fmaxf(mx, __shfl_xor_sync(0xffffffffu, mx, off));
            float mn = fmaxf(m_[j], mx);
            float al = __expf(m_[j] - mn);
            float p0 = __expf(sa - mn), p1 = __expf(sb - mn);
            float rs = p0 + p1;
#pragma unroll
            for (int off = 16; off > 0; off >>= 1)
                rs += __shfl_xor_sync(0xffffffffu, rs, off);
            l_[j] = l_[j] * al + rs;
            m_[j] = mn;
            Oacc[j] = fma2(pack2(al, al), Oacc[j], 0ull);
            *(float2*)&Psd[2 * tx][8 * ty + 2 * j]     = make_float2(p0, p0);
            *(float2*)&Psd[2 * tx + 1][8 * ty + 2 * j] = make_float2(p1, p1);
        }
        __syncthreads();
#pragma unroll 16
        for (int key = 0; key < 64; key++) {
            const u64* pp = (const u64*)&Psd[key][8 * ty];
            u64 vv = *(const u64*)&Vt[key][2 * tx];
            Oacc[0] = fma2(pp[0], vv, Oacc[0]);
            Oacc[1] = fma2(pp[1], vv, Oacc[1]);
            Oacc[2] = fma2(pp[2], vv, Oacc[2]);
            Oacc[3] = fma2(pp[3], vv, Oacc[3]);
        }
    }
#pragma unroll
    for (int j = 0; j < 4; j++) {
        float inv = 1.f / l_[j];
        float o0, o1; unpack2(Oacc[j], o0, o1);
        size_t base = ((size_t)(b * TG2) + q0 + 4 * ty + j) * 64 + 2 * tx;
        g_hg[base]     = o0 * inv;
        g_hg[base + 1] = o1 * inv;
    }
}

// ------- K8: hp = V*wm^T MMA, pre-split h/l smem, K-step 16 -------
#define HAS 136
#define HBS 216
__global__ __launch_bounds__(256, 2) void k_hp() {
    int b = blockIdx.y;
    int s0 = blockIdx.x * 128;
    const float* V = g_v + (size_t)b * NPB;
    const float* W = g_wmT + (size_t)b * (P2 * P2P);
    __shared__ __align__(16) unsigned Avh[16][HAS], Avl[16][HAS];
    __shared__ __align__(16) unsigned Bwh[16][HBS], Bwl[16][HBS];
    int t = threadIdx.x;
    for (int i = t; i < 16 * HAS; i += 256) { ((unsigned*)Avh)[i] = 0; ((unsigned*)Avl)[i] = 0; }
    for (int i = t; i < 16 * HBS; i += 256) { ((unsigned*)Bwh)[i] = 0; ((unsigned*)Bwl)[i] = 0; }
    int lane = t & 31, w = t >> 5;
    int gid = lane >> 2, tig = lane & 3;
    int m0 = w * 16;
    float acc[25][4];
#pragma unroll
    for (int nt = 0; nt < 25; nt++) { acc[nt][0] = acc[nt][1] = acc[nt][2] = acc[nt][3] = 0.f; }

    for (int k0 = 0; k0 < 208; k0 += 16) {
        __syncthreads();
        for (int ii = 0; ii < 2; ii++) {           // V tile: 128 rows x 4 float4
            int i = 2 * t + ii;
            int r = i >> 2, kq = i & 3;
            int kbase = k0 + kq * 4;
            float4 vv = make_float4(0.f, 0.f, 0.f, 0.f);
            if (kbase < 196) vv = *(const float4*)(V + (size_t)(s0 + r) * 196 + kbase);
            unsigned h, l;
            split2(vv.x, h, l); Avh[kq * 4 + 0][r] = h; Avl[kq * 4 + 0][r] = l;
            split2(vv.y, h, l); Avh[kq * 4 + 1][r] = h; Avl[kq * 4 + 1][r] = l;
            split2(vv.z, h, l); Avh[kq * 4 + 2][r] = h; Avl[kq * 4 + 2][r] = l;
            split2(vv.w, h, l); Avh[kq * 4 + 3][r] = h; Avl[kq * 4 + 3][r] = l;
        }
        for (int i = t; i < 800; i += 256) {       // W tile: 16 rows x 50 float4
            int r = i / 50, c4 = i - (i / 50) * 50;
            int kg = k0 + r;
            float4 wv = make_float4(0.f, 0.f, 0.f, 0.f);
            if (kg < 196) wv = *(const float4*)(W + (size_t)kg * P2P + c4 * 4);
            uint4 h, l;
            split2(wv.x, h.x, l.x); split2(wv.y, h.y, l.y);
            split2(wv.z, h.z, l.z); split2(wv.w, h.w, l.w);
            *(uint4*)&Bwh[r][c4 * 4] = h; *(uint4*)&Bwl[r][c4 * 4] = l;
        }
        __syncthreads();
#pragma unroll
        for (int sub = 0; sub < 2; sub++) {
            int ra = sub * 8 + tig, rb = ra + 4;
            unsigned ah0 = Avh[ra][m0 + gid], ah1 = Avh[ra][m0 + gid + 8];
            unsigned ah2 = Avh[rb][m0 + gid], ah3 = Avh[rb][m0 + gid + 8];
            unsigned al0 = Avl[ra][m0 + gid], al1 = Avl[ra][m0 + gid + 8];
            unsigned al2 = Avl[rb][m0 + gid], al3 = Avl[rb][m0 + gid + 8];
#pragma unroll
            for (int nt = 0; nt < 25; nt++) {
                int n0 = nt * 8;
                unsigned bh0 = Bwh[ra][n0 + gid], bh1 = Bwh[rb][n0 + gid];
                unsigned bl0 = Bwl[ra][n0 + gid], bl1 = Bwl[rb][n0 + gid];
                mma_tf32(acc[nt], ah0, ah1, ah2, ah3, bh0, bh1);
                mma_tf32(acc[nt], ah0, ah1, ah2, ah3, bl0, bl1);
                mma_tf32(acc[nt], al0, al1, al2, al3, bh0, bh1);
            }
        }
    }
    float* O = g_hin + (size_t)b * NPB;
    size_t r0 = (size_t)(s0 + m0 + gid) * 196;
    size_t r1 = r0 + 8 * 196;
#pragma unroll
    for (int nt = 0; nt < 25; nt++) {
        int q0 = nt * 8 + 2 * tig;
        if (q0 < 196) {
            O[r0 + q0] = acc[nt][0];
            O[r1 + q0] = acc[nt][2];
            if (q0 + 1 < 196) {
                O[r0 + q0 + 1] = acc[nt][1];
                O[r1 + q0 + 1] = acc[nt][3];
            }
        }
    }
}

// ---------------- K9: proj fused blend + conv + residual, FFMA2 ----------------
__global__ __launch_bounds__(128) void k_proj(const float* __restrict__ x,
                                              const float* __restrict__ pw,
                                              float* __restrict__ out) {
    __shared__ __align__(16) float sH[64][128];
    __shared__ __align__(16) float sWt[64][64];
    int b = blockIdx.y;
    int pix0 = blockIdx.x * 128;
    int t = threadIdx.x;

    for (int i = t; i < 2048; i += 128) {
        int c = i >> 5, p4 = i & 31;
        int pgl = pix0 + p4 * 4;
        int h = pgl / WID, w = pgl - h * WID;
        int cell = (h >> 3) * 56 + (w >> 3);
        float4 hp = *(const float4*)(g_hin + (size_t)b * NPB + (size_t)c * HW + pgl);
        float hg = g_hg[(size_t)(b * TG2 + cell) * 64 + c] * 0.25f;
        float4 r = make_float4(0.75f * hp.x + hg, 0.75f * hp.y + hg,
                               0.75f * hp.z + hg, 0.75f * hp.w + hg);
        *(float4*)&sH[c][p4 * 4] = r;
    }
    for (int i = t; i < 1024; i += 128) {
        int o = i & 63, c4 = i >> 6;
        float4 w = *(const float4*)(pw + o * 64 + c4 * 4);
        sWt[c4 * 4 + 0][o] = w.x;
        sWt[c4 * 4 + 1][o] = w.y;
        sWt[c4 * 4 + 2][o] = w.z;
        sWt[c4 * 4 + 3][o] = w.w;
    }
    __syncthreads();

    int og = t >> 4, pg = t & 15;
    u64 accp[8][4];
#pragma unroll
    for (int i = 0; i < 8; i++)
#pragma unroll
        for (int j = 0; j < 4; j++) accp[i][j] = 0ull;

#pragma unroll 8
    for (int c = 0; c < 64; c++) {
        const u64* xp = (const u64*)&sH[c][pg * 4];
        const u64* xq = (const u64*)&sH[c][pg * 4 + 64];
        u64 x0 = xp[0], x1 = xp[1], x2 = xq[0], x3 = xq[1];
        float4 w0 = *(const float4*)&sWt[c][og * 4];
        float4 w1 = *(const float4*)&sWt[c][og * 4 + 32];
        float aw[8] = {w0.x, w0.y, w0.z, w0.w, w1.x, w1.y, w1.z, w1.w};
#pragma unroll
        for (int i = 0; i < 8; i++) {
            u64 ad = pack2(aw[i], aw[i]);
            accp[i][0] = fma2(ad, x0, accp[i][0]);
            accp[i][1] = fma2(ad, x1, accp[i][1]);
            accp[i][2] = fma2(ad, x2, accp[i][2]);
            accp[i][3] = fma2(ad, x3, accp[i][3]);
        }
    }
#pragma unroll
    for (int i = 0; i < 8; i++) {
        int o = og * 4 + ((i < 4) ? i : 28 + i);
        size_t base = ((size_t)b * CC + o) * HW + pix0;
        float4 xr0 = *(const float4*)(x + base + pg * 4);
        float4 xr1 = *(const float4*)(x + base + 64 + pg * 4);
        float l0, h0, l1, h1;
        unpack2(accp[i][0], l0, h0); unpack2(accp[i][1], l1, h1);
        *(float4*)(out + base + pg * 4) =
            make_float4(l0 + xr0.x, h0 + xr0.y, l1 + xr0.z, h1 + xr0.w);
        unpack2(accp[i][2], l0, h0); unpack2(accp[i][3], l1, h1);
        *(float4*)(out + base + 64 + pg * 4) =
            make_float4(l0 + xr1.x, h0 + xr1.y, l1 + xr1.z, h1 + xr1.w);
    }
}

extern "C" void kernel_launch(void* const* d_in, const int* in_sizes, int n_in,
                              void* d_out, int out_size) {
    const float* x   = (const float*)d_in[0];
    const float* gnw = (const float*)d_in[1];
    const float* gnb = (const float*)d_in[2];
    const float* qw  = (const float*)d_in[3];
    const float* qb  = (const float*)d_in[4];
    const float* kw  = (const float*)d_in[5];
    const float* kb  = (const float*)d_in[6];
    const float* vw  = (const float*)d_in[7];
    const float* vb  = (const float*)d_in[8];
    const float* pw  = (const float*)d_in[9];
    float* out = (float*)d_out;

    k_pool_stats<<<dim3(784, BATCH), 256>>>(x);
    k_stats2<<<BATCH, 256>>>();
    k_qkvg<<<dim3(TG2, BATCH), 64>>>(gnw, gnb, qw, qb, kw, kb, vw, vb);
    k_qkv<<<dim3(HW / 128, BATCH), 128>>>(x, gnw, gnb, qw, qb, kw, kb, vw, vb);
    k_wm<<<dim3(GRIDK, BATCH), 416>>>();
    k_softmax_wm<<<dim3(P2, BATCH), 256>>>();
    k_gattn<<<dim3(TG2 / 32, BATCH), 256>>>();
    k_hp<<<dim3(SPB / 128, BATCH), 256>>>();
    k_proj<<<dim3(HW / 128, BATCH), 128>>>(x, pw, out);
}